// round 1
// baseline (speedup 1.0000x reference)
#include <cuda_runtime.h>
#include <math.h>

#define C        256
#define HEADS    8
#define BATCH    8
#define HH       56
#define WW       56
#define NQ       (HH*WW)    /* 3136 */
#define HK       28
#define WK       28
#define NKV      (HK*WK)    /* 784 */
#define DH       32
#define EPS_BN   1e-5f

/* -------- scratch (device globals; no runtime allocation) -------- */
__device__ float g_tq[BATCH * NQ  * C];          // dw+bn output for q, layout (b, n, c)
__device__ float g_tk[BATCH * NKV * C];          // dw+bn output for k, layout (b, n', c)
__device__ float g_tv[BATCH * NKV * C];          // dw+bn output for v
__device__ float g_q [BATCH * HEADS * NQ  * DH]; // (b, h, n, d)
__device__ float g_k [BATCH * HEADS * NKV * DH];
__device__ float g_v [BATCH * HEADS * NKV * DH];
__device__ float g_oa[BATCH * NQ * C];           // attention out, layout (b, n, c)

/* =================================================================
 * Depthwise 3x3 stride 1 + bias + BN (inference), for Q path.
 * x: (b, n, c) channel-contiguous. Output: (b, n, c).
 * grid (NQ, B), block C threads (thread = channel -> coalesced).
 * ================================================================= */
__global__ void dw_bn_s1(const float* __restrict__ x,
                         const float* __restrict__ w,   const float* __restrict__ dwb,
                         const float* __restrict__ gmm, const float* __restrict__ bet,
                         const float* __restrict__ rm,  const float* __restrict__ rv,
                         float* __restrict__ out)
{
    const int n = blockIdx.x, b = blockIdx.y, c = threadIdx.x;
    const int y = n / WW, x0 = n % WW;
    const float* xb = x + (size_t)b * NQ * C + c;
    float acc = 0.f;
    #pragma unroll
    for (int dy = 0; dy < 3; dy++) {
        const int yy = y + dy - 1;
        if (yy < 0 || yy >= HH) continue;
        #pragma unroll
        for (int dx = 0; dx < 3; dx++) {
            const int xx = x0 + dx - 1;
            if (xx < 0 || xx >= WW) continue;
            acc += xb[(size_t)(yy * WW + xx) * C] * w[c * 9 + dy * 3 + dx];
        }
    }
    acc += dwb[c];
    const float s = gmm[c] * rsqrtf(rv[c] + EPS_BN);
    out[((size_t)b * NQ + n) * C + c] = acc * s + (bet[c] - rm[c] * s);
}

/* =================================================================
 * Fused depthwise 3x3 stride 2 + bias + BN for K and V (share x reads).
 * grid (NKV, B), block C.
 * ================================================================= */
__global__ void dw_bn_s2(const float* __restrict__ x,
                         const float* __restrict__ kw, const float* __restrict__ kdwb,
                         const float* __restrict__ kg, const float* __restrict__ kb,
                         const float* __restrict__ km, const float* __restrict__ kvv,
                         const float* __restrict__ vw, const float* __restrict__ vdwb,
                         const float* __restrict__ vg, const float* __restrict__ vb,
                         const float* __restrict__ vm, const float* __restrict__ vvv,
                         float* __restrict__ outk, float* __restrict__ outv)
{
    const int n = blockIdx.x, b = blockIdx.y, c = threadIdx.x;
    const int yp = n / WK, xp = n % WK;
    const float* xb = x + (size_t)b * NQ * C + c;
    float ak = 0.f, av = 0.f;
    #pragma unroll
    for (int dy = 0; dy < 3; dy++) {
        const int yy = 2 * yp + dy - 1;
        if (yy < 0 || yy >= HH) continue;
        #pragma unroll
        for (int dx = 0; dx < 3; dx++) {
            const int xx = 2 * xp + dx - 1;
            if (xx < 0 || xx >= WW) continue;
            const float xv = xb[(size_t)(yy * WW + xx) * C];
            ak += xv * kw[c * 9 + dy * 3 + dx];
            av += xv * vw[c * 9 + dy * 3 + dx];
        }
    }
    ak += kdwb[c];
    av += vdwb[c];
    const float sk = kg[c] * rsqrtf(kvv[c] + EPS_BN);
    const float sv = vg[c] * rsqrtf(vvv[c] + EPS_BN);
    const size_t o = ((size_t)b * NKV + n) * C + c;
    outk[o] = ak * sk + (kb[c] - km[c] * sk);
    outv[o] = av * sv + (vb[c] - vm[c] * sv);
}

/* =================================================================
 * NT GEMM: out[b][o][n] = sum_c A[o][c] * B[b][n][c] + bias[o]
 * M = K = 256 fixed, Nsp runtime. Both operands K-contiguous.
 * Tile 64x64x16, 256 threads, 4x4 micro-tile.
 * mode 0: store head-split (b, o>>5, n, o&31)   [q/k/v]
 * mode 1: store linear    (b, n, o)             [proj -> d_out]
 * grid (ceil(Nsp/64), 4, B)
 * ================================================================= */
__global__ void gemm_nt(const float* __restrict__ A, const float* __restrict__ B,
                        const float* __restrict__ bias, float* __restrict__ out,
                        int Nsp, int mode)
{
    __shared__ float As[16][64];
    __shared__ float Bs[16][64];
    const int b  = blockIdx.z;
    const int n0 = blockIdx.x * 64;
    const int o0 = blockIdx.y * 64;
    const float* Bb = B + (size_t)b * Nsp * C;
    const int tid = threadIdx.x;
    const int lr = tid >> 2;            // 0..63  (row within tile)
    const int lc = (tid & 3) << 2;      // 0,4,8,12 (K offset, float4)
    const int tx = tid & 15;            // n micro-group
    const int ty = tid >> 4;            // o micro-group

    float cc[4][4];
    #pragma unroll
    for (int i = 0; i < 4; i++)
        #pragma unroll
        for (int j = 0; j < 4; j++) cc[i][j] = 0.f;

    const float* Aptr  = A  + (size_t)(o0 + lr) * C + lc;
    const float* Bptr  = Bb + (size_t)(n0 + lr) * C + lc;
    const bool bvalid  = (n0 + lr) < Nsp;

    for (int k0 = 0; k0 < C; k0 += 16) {
        const float4 av = *(const float4*)(Aptr + k0);
        float4 bv = make_float4(0.f, 0.f, 0.f, 0.f);
        if (bvalid) bv = *(const float4*)(Bptr + k0);
        __syncthreads();
        As[lc + 0][lr] = av.x; As[lc + 1][lr] = av.y;
        As[lc + 2][lr] = av.z; As[lc + 3][lr] = av.w;
        Bs[lc + 0][lr] = bv.x; Bs[lc + 1][lr] = bv.y;
        Bs[lc + 2][lr] = bv.z; Bs[lc + 3][lr] = bv.w;
        __syncthreads();
        #pragma unroll
        for (int kk = 0; kk < 16; kk++) {
            const float4 a4 = *(const float4*)&As[kk][ty << 2];
            const float4 b4 = *(const float4*)&Bs[kk][tx << 2];
            cc[0][0] += a4.x * b4.x; cc[0][1] += a4.x * b4.y;
            cc[0][2] += a4.x * b4.z; cc[0][3] += a4.x * b4.w;
            cc[1][0] += a4.y * b4.x; cc[1][1] += a4.y * b4.y;
            cc[1][2] += a4.y * b4.z; cc[1][3] += a4.y * b4.w;
            cc[2][0] += a4.z * b4.x; cc[2][1] += a4.z * b4.y;
            cc[2][2] += a4.z * b4.z; cc[2][3] += a4.z * b4.w;
            cc[3][0] += a4.w * b4.x; cc[3][1] += a4.w * b4.y;
            cc[3][2] += a4.w * b4.z; cc[3][3] += a4.w * b4.w;
        }
    }

    #pragma unroll
    for (int i = 0; i < 4; i++) {
        const int o = o0 + (ty << 2) + i;
        const float bi = bias[o];
        #pragma unroll
        for (int j = 0; j < 4; j++) {
            const int n = n0 + (tx << 2) + j;
            if (n < Nsp) {
                const float val = cc[i][j] + bi;
                if (mode == 0)
                    out[(((size_t)b * HEADS + (o >> 5)) * Nsp + n) * DH + (o & 31)] = val;
                else
                    out[((size_t)b * Nsp + n) * C + o] = val;
            }
        }
    }
}

/* =================================================================
 * Flash-style attention. q: (b,h,NQ,32), k/v: (b,h,NKV,32).
 * Block = 256 threads = 8 warps; 32 queries/block (4 per warp).
 * K/V staged in smem in 32-key tiles; online softmax in registers.
 * Output written to (b, n, c) layout (coalesced 128B per warp).
 * grid (NQ/32, HEADS, B)
 * ================================================================= */
__global__ void attn_kernel(const float* __restrict__ q, const float* __restrict__ k,
                            const float* __restrict__ v, float* __restrict__ out)
{
    __shared__ float qs[32][33];
    __shared__ float ks[32][33];
    __shared__ float vs[32][32];
    __shared__ float ps[8][4][32];

    const int b = blockIdx.z, h = blockIdx.y;
    const int i0 = blockIdx.x * 32;
    const int tid = threadIdx.x;
    const int wid = tid >> 5, lane = tid & 31;

    const float* qb = q + (((size_t)b * HEADS + h) * NQ + i0) * DH;
    const float* kb = k + ((size_t)b * HEADS + h) * NKV * DH;
    const float* vb = v + ((size_t)b * HEADS + h) * NKV * DH;

    #pragma unroll
    for (int p = 0; p < 4; p++) {
        const int r = wid + p * 8;
        qs[r][lane] = qb[(size_t)r * DH + lane];
    }

    float m[4], l[4], acc[4];
    #pragma unroll
    for (int qi = 0; qi < 4; qi++) { m[qi] = -1e30f; l[qi] = 0.f; acc[qi] = 0.f; }
    const float scale = 0.17677669529663688f; /* 32^-0.5 */

    for (int j0 = 0; j0 < NKV; j0 += 32) {
        __syncthreads();
        #pragma unroll
        for (int p = 0; p < 4; p++) {
            const int jj = wid + p * 8;
            const int j = j0 + jj;
            float kv = 0.f, vv = 0.f;
            if (j < NKV) {
                kv = kb[(size_t)j * DH + lane];
                vv = vb[(size_t)j * DH + lane];
            }
            ks[jj][lane] = kv;
            vs[jj][lane] = vv;
        }
        __syncthreads();

        /* scores: lane owns key j0+lane, computes 4 query dots */
        float s[4] = {0.f, 0.f, 0.f, 0.f};
        #pragma unroll
        for (int dd = 0; dd < DH; dd++) {
            const float kv = ks[lane][dd];
            #pragma unroll
            for (int qi = 0; qi < 4; qi++)
                s[qi] += qs[(wid << 2) + qi][dd] * kv;
        }
        const bool valid = (j0 + lane) < NKV;

        #pragma unroll
        for (int qi = 0; qi < 4; qi++) {
            const float sv = valid ? s[qi] * scale : -1e30f;
            float tm = sv;
            #pragma unroll
            for (int off = 16; off; off >>= 1)
                tm = fmaxf(tm, __shfl_xor_sync(0xffffffffu, tm, off));
            const float nm = fmaxf(m[qi], tm);
            const float pv = __expf(sv - nm);
            float ts = pv;
            #pragma unroll
            for (int off = 16; off; off >>= 1)
                ts += __shfl_xor_sync(0xffffffffu, ts, off);
            const float corr = __expf(m[qi] - nm);
            l[qi] = l[qi] * corr + ts;
            m[qi] = nm;
            acc[qi] *= corr;
            ps[wid][qi][lane] = pv;
        }
        __syncwarp();

        /* acc[qi][lane] += sum_jj p[qi][jj] * v[jj][lane] */
        #pragma unroll
        for (int jj = 0; jj < 32; jj++) {
            const float vv = vs[jj][lane];
            #pragma unroll
            for (int qi = 0; qi < 4; qi++)
                acc[qi] += ps[wid][qi][jj] * vv;
        }
    }

    #pragma unroll
    for (int qi = 0; qi < 4; qi++) {
        const int i = i0 + (wid << 2) + qi;
        out[((size_t)b * NQ + i) * C + h * DH + lane] = acc[qi] / l[qi];
    }
}

/* ================================================================= */
extern "C" void kernel_launch(void* const* d_in, const int* in_sizes, int n_in,
                              void* d_out, int out_size)
{
    /* robust to presence/absence of H, W scalar inputs:
       26 parameter tensors follow x (and optional H, W) */
    const int base = n_in - 26;
    const float* x = (const float*)d_in[0];
    auto in = [&](int i) { return (const float*)d_in[base + i]; };
    /* group layout (per path p in q,k,v): dw_w, dw_b, bn_g, bn_b, bn_m, bn_v, pw_w, pw_b
       q: 0..7  k: 8..15  v: 16..23  proj_w: 24  proj_b: 25 */

    float *tq, *tk, *tv, *qh, *kh, *vh, *oa;
    cudaGetSymbolAddress((void**)&tq, g_tq);
    cudaGetSymbolAddress((void**)&tk, g_tk);
    cudaGetSymbolAddress((void**)&tv, g_tv);
    cudaGetSymbolAddress((void**)&qh, g_q);
    cudaGetSymbolAddress((void**)&kh, g_k);
    cudaGetSymbolAddress((void**)&vh, g_v);
    cudaGetSymbolAddress((void**)&oa, g_oa);

    dw_bn_s1<<<dim3(NQ, BATCH), C>>>(x, in(0), in(1), in(2), in(3), in(4), in(5), tq);
    dw_bn_s2<<<dim3(NKV, BATCH), C>>>(x,
                                      in(8),  in(9),  in(10), in(11), in(12), in(13),
                                      in(16), in(17), in(18), in(19), in(20), in(21),
                                      tk, tv);

    gemm_nt<<<dim3((NQ  + 63) / 64, 4, BATCH), 256>>>(in(6),  tq, in(7),  qh, NQ,  0);
    gemm_nt<<<dim3((NKV + 63) / 64, 4, BATCH), 256>>>(in(14), tk, in(15), kh, NKV, 0);
    gemm_nt<<<dim3((NKV + 63) / 64, 4, BATCH), 256>>>(in(22), tv, in(23), vh, NKV, 0);

    attn_kernel<<<dim3(NQ / 32, HEADS, BATCH), 256>>>(qh, kh, vh, oa);

    gemm_nt<<<dim3((NQ + 63) / 64, 4, BATCH), 256>>>(in(24), oa, in(25), (float*)d_out, NQ, 1);
}

// round 2
// speedup vs baseline: 1.1858x; 1.1858x over previous
#include <cuda_runtime.h>
#include <math.h>

#define C        256
#define HEADS    8
#define BATCH    8
#define HH       56
#define WW       56
#define NQ       (HH*WW)    /* 3136 */
#define HK       28
#define WK       28
#define NKV      (HK*WK)    /* 784 */
#define DH       32
#define EPS_BN   1e-5f

typedef unsigned long long u64;

/* ---------------- f32x2 helpers (FFMA2 path) ---------------- */
__device__ __forceinline__ u64 fma2(u64 a, u64 b, u64 c) {
    u64 d;
    asm("fma.rn.f32x2 %0, %1, %2, %3;" : "=l"(d) : "l"(a), "l"(b), "l"(c));
    return d;
}
__device__ __forceinline__ u64 mul2(u64 a, u64 b) {
    u64 d;
    asm("mul.rn.f32x2 %0, %1, %2;" : "=l"(d) : "l"(a), "l"(b));
    return d;
}
__device__ __forceinline__ u64 pack2(float a, float b) {
    u64 d;
    asm("mov.b64 %0, {%1, %2};" : "=l"(d) : "f"(a), "f"(b));
    return d;
}
__device__ __forceinline__ void unpack2(u64 p, float& a, float& b) {
    asm("mov.b64 {%0, %1}, %2;" : "=f"(a), "=f"(b) : "l"(p));
}

/* -------- scratch (device globals; no runtime allocation) -------- */
__device__ float g_tq[BATCH * NQ  * C];
__device__ float g_tk[BATCH * NKV * C];
__device__ float g_tv[BATCH * NKV * C];
__device__ float g_q [BATCH * HEADS * NQ  * DH];
__device__ float g_k [BATCH * HEADS * NKV * DH];
__device__ float g_v [BATCH * HEADS * NKV * DH];
__device__ float g_oa[BATCH * NQ * C];

/* =================================================================
 * Depthwise 3x3 stride 1 + bias + BN (Q path). (b,n,c) layouts.
 * ================================================================= */
__global__ void dw_bn_s1(const float* __restrict__ x,
                         const float* __restrict__ w,   const float* __restrict__ dwb,
                         const float* __restrict__ gmm, const float* __restrict__ bet,
                         const float* __restrict__ rm,  const float* __restrict__ rv,
                         float* __restrict__ out)
{
    const int n = blockIdx.x, b = blockIdx.y, c = threadIdx.x;
    const int y = n / WW, x0 = n % WW;
    const float* xb = x + (size_t)b * NQ * C + c;
    float acc = 0.f;
    #pragma unroll
    for (int dy = 0; dy < 3; dy++) {
        const int yy = y + dy - 1;
        if (yy < 0 || yy >= HH) continue;
        #pragma unroll
        for (int dx = 0; dx < 3; dx++) {
            const int xx = x0 + dx - 1;
            if (xx < 0 || xx >= WW) continue;
            acc += xb[(size_t)(yy * WW + xx) * C] * w[c * 9 + dy * 3 + dx];
        }
    }
    acc += dwb[c];
    const float s = gmm[c] * rsqrtf(rv[c] + EPS_BN);
    out[((size_t)b * NQ + n) * C + c] = acc * s + (bet[c] - rm[c] * s);
}

/* ===== Depthwise 3x3 stride 2 + bias + BN, fused K and V ===== */
__global__ void dw_bn_s2(const float* __restrict__ x,
                         const float* __restrict__ kw, const float* __restrict__ kdwb,
                         const float* __restrict__ kg, const float* __restrict__ kb,
                         const float* __restrict__ km, const float* __restrict__ kvv,
                         const float* __restrict__ vw, const float* __restrict__ vdwb,
                         const float* __restrict__ vg, const float* __restrict__ vb,
                         const float* __restrict__ vm, const float* __restrict__ vvv,
                         float* __restrict__ outk, float* __restrict__ outv)
{
    const int n = blockIdx.x, b = blockIdx.y, c = threadIdx.x;
    const int yp = n / WK, xp = n % WK;
    const float* xb = x + (size_t)b * NQ * C + c;
    float ak = 0.f, av = 0.f;
    #pragma unroll
    for (int dy = 0; dy < 3; dy++) {
        const int yy = 2 * yp + dy - 1;
        if (yy < 0 || yy >= HH) continue;
        #pragma unroll
        for (int dx = 0; dx < 3; dx++) {
            const int xx = 2 * xp + dx - 1;
            if (xx < 0 || xx >= WW) continue;
            const float xv = xb[(size_t)(yy * WW + xx) * C];
            ak += xv * kw[c * 9 + dy * 3 + dx];
            av += xv * vw[c * 9 + dy * 3 + dx];
        }
    }
    ak += kdwb[c];
    av += vdwb[c];
    const float sk = kg[c] * rsqrtf(kvv[c] + EPS_BN);
    const float sv = vg[c] * rsqrtf(vvv[c] + EPS_BN);
    const size_t o = ((size_t)b * NKV + n) * C + c;
    outk[o] = ak * sk + (kb[c] - km[c] * sk);
    outv[o] = av * sv + (vb[c] - vm[c] * sv);
}

/* =================================================================
 * FFMA2 NT GEMM: out[b][o][n] = sum_c A[o][c] * B[b][n][c] + bias[o]
 * M=K=256. Tile 128x64x16, 256 threads, micro 8(rows o) x 4(cols n)
 * via f32x2 pairs along n: thread tx owns cols {2tx,2tx+1,2tx+32,2tx+33}.
 * A stored duplicated (v,v) in smem so a-operand is a direct LDS.
 * mode 0: out head-split (b, o>>5, n, o&31);  mode 1: out (b, n, o).
 * grid (ceil(Nsp/64), 2, B)
 * ================================================================= */
__global__ __launch_bounds__(256) void gemm2(const float* __restrict__ A,
                                             const float* __restrict__ B,
                                             const float* __restrict__ bias,
                                             float* __restrict__ out,
                                             int Nsp, int mode)
{
    __shared__ __align__(16) float2 As2[16][128];   /* 16 KB, (a,a) duplicated */
    __shared__ __align__(16) float  Bs [16][64];    /* 4 KB */

    const int b  = blockIdx.z;
    const int n0 = blockIdx.x * 64;
    const int o0 = blockIdx.y * 128;
    const int tid = threadIdx.x;
    const int tx = tid & 15, ty = tid >> 4;
    const float* Bb = B + (size_t)b * Nsp * C;

    /* fill indexing */
    const int ar  = tid >> 1;              /* 0..127: A row within tile */
    const int aks = (tid & 1) * 8;         /* A k-offset: 0 or 8 */
    const int br  = tid >> 2;              /* 0..63 : B row within tile */
    const int bks = (tid & 3) * 4;         /* B k-offset */
    const bool bval = (n0 + br) < Nsp;
    const float* Ap = A  + (size_t)(o0 + ar) * C + aks;
    const float* Bp = Bb + (size_t)(n0 + br) * C + bks;

    u64 acc[8][2];
    #pragma unroll
    for (int i = 0; i < 8; i++) { acc[i][0] = 0ull; acc[i][1] = 0ull; }

    for (int k0 = 0; k0 < C; k0 += 16) {
        const float4 a0 = *(const float4*)(Ap + k0);
        const float4 a1 = *(const float4*)(Ap + k0 + 4);
        float4 bvv = make_float4(0.f, 0.f, 0.f, 0.f);
        if (bval) bvv = *(const float4*)(Bp + k0);
        __syncthreads();
        As2[aks + 0][ar] = make_float2(a0.x, a0.x);
        As2[aks + 1][ar] = make_float2(a0.y, a0.y);
        As2[aks + 2][ar] = make_float2(a0.z, a0.z);
        As2[aks + 3][ar] = make_float2(a0.w, a0.w);
        As2[aks + 4][ar] = make_float2(a1.x, a1.x);
        As2[aks + 5][ar] = make_float2(a1.y, a1.y);
        As2[aks + 6][ar] = make_float2(a1.z, a1.z);
        As2[aks + 7][ar] = make_float2(a1.w, a1.w);
        Bs[bks + 0][br] = bvv.x;
        Bs[bks + 1][br] = bvv.y;
        Bs[bks + 2][br] = bvv.z;
        Bs[bks + 3][br] = bvv.w;
        __syncthreads();
        #pragma unroll
        for (int kk = 0; kk < 16; kk++) {
            const ulonglong2* ap = (const ulonglong2*)&As2[kk][ty * 8];
            const u64 b0 = *(const u64*)&Bs[kk][2 * tx];
            const u64 b1 = *(const u64*)&Bs[kk][2 * tx + 32];
            #pragma unroll
            for (int i2 = 0; i2 < 4; i2++) {
                const ulonglong2 av = ap[i2];
                acc[2*i2+0][0] = fma2(av.x, b0, acc[2*i2+0][0]);
                acc[2*i2+0][1] = fma2(av.x, b1, acc[2*i2+0][1]);
                acc[2*i2+1][0] = fma2(av.y, b0, acc[2*i2+1][0]);
                acc[2*i2+1][1] = fma2(av.y, b1, acc[2*i2+1][1]);
            }
        }
    }

    #pragma unroll
    for (int i = 0; i < 8; i++) {
        const int o = o0 + ty * 8 + i;
        const float bi = bias[o];
        #pragma unroll
        for (int u = 0; u < 2; u++) {
            float v0, v1;
            unpack2(acc[i][u], v0, v1);
            const int n = n0 + 2 * tx + 32 * u;
            if (n < Nsp) {
                if (mode == 0) {
                    float* dst = out + (((size_t)b * HEADS + (o >> 5)) * Nsp + n) * DH + (o & 31);
                    dst[0] = v0 + bi;
                    if (n + 1 < Nsp) dst[DH] = v1 + bi;
                } else {
                    float* dst = out + ((size_t)b * Nsp + n) * C + o;
                    dst[0] = v0 + bi;
                    if (n + 1 < Nsp) dst[C] = v1 + bi;
                }
            }
        }
    }
}

/* =================================================================
 * FFMA2 flash attention, thread-per-query (no shuffles).
 * q,k,v: (b,h,n,32). Block 256 threads = 256 queries.
 * 16-key smem tiles; all lanes broadcast-read the same key row.
 * Online softmax fully thread-local. Out: (b,n,c).
 * grid (ceil(NQ/256), HEADS, B)
 * ================================================================= */
__global__ __launch_bounds__(256) void attn2(const float* __restrict__ q,
                                             const float* __restrict__ k,
                                             const float* __restrict__ v,
                                             float* __restrict__ out)
{
    __shared__ __align__(16) float ks[16][32];
    __shared__ __align__(16) float vs[16][32];

    const int b = blockIdx.z, h = blockIdx.y;
    const int n = blockIdx.x * 256 + threadIdx.x;
    const bool active = n < NQ;
    const size_t bh = (size_t)b * HEADS + h;
    const float* kb = k + bh * NKV * DH;
    const float* vb = v + bh * NKV * DH;
    const float scale = 0.17677669529663688f; /* 32^-0.5 */

    /* q (pre-scaled) into 16 f32x2 regs */
    u64 q2[16];
    if (active) {
        const ulonglong2* qp = (const ulonglong2*)(q + (bh * NQ + n) * DH);
        const u64 sc2 = pack2(scale, scale);
        #pragma unroll
        for (int t = 0; t < 8; t++) {
            const ulonglong2 qv = qp[t];
            q2[2*t+0] = mul2(qv.x, sc2);
            q2[2*t+1] = mul2(qv.y, sc2);
        }
    } else {
        #pragma unroll
        for (int t = 0; t < 16; t++) q2[t] = 0ull;
    }

    u64 acc[16];
    #pragma unroll
    for (int t = 0; t < 16; t++) acc[t] = 0ull;
    float m = -1e30f, l = 0.f;

    const int jj = threadIdx.x >> 4;            /* tile-fill: key row   */
    const int dd = (threadIdx.x & 15) * 2;      /* tile-fill: d offset  */

    for (int j0 = 0; j0 < NKV; j0 += 16) {
        __syncthreads();
        *(float2*)&ks[jj][dd] = *(const float2*)(kb + (size_t)(j0 + jj) * DH + dd);
        *(float2*)&vs[jj][dd] = *(const float2*)(vb + (size_t)(j0 + jj) * DH + dd);
        __syncthreads();

        /* scores for 16 keys */
        float s[16];
        #pragma unroll
        for (int t = 0; t < 16; t++) {
            const ulonglong2* kr = (const ulonglong2*)ks[t];
            u64 s0 = 0ull, s1 = 0ull;
            #pragma unroll
            for (int d4 = 0; d4 < 8; d4++) {
                const ulonglong2 kv = kr[d4];
                s0 = fma2(q2[2*d4+0], kv.x, s0);
                s1 = fma2(q2[2*d4+1], kv.y, s1);
            }
            float a0, a1, b0, b1;
            unpack2(s0, a0, a1);
            unpack2(s1, b0, b1);
            s[t] = (a0 + a1) + (b0 + b1);
        }

        /* tile max + rescale */
        float tm = s[0];
        #pragma unroll
        for (int t = 1; t < 16; t++) tm = fmaxf(tm, s[t]);
        const float nm = fmaxf(m, tm);
        const float corr = __expf(m - nm);
        m = nm;
        l *= corr;
        const u64 c2 = pack2(corr, corr);
        #pragma unroll
        for (int t = 0; t < 16; t++) acc[t] = mul2(acc[t], c2);

        /* exp + PV */
        #pragma unroll
        for (int t = 0; t < 16; t++) {
            const float p = __expf(s[t] - nm);
            l += p;
            const u64 p2 = pack2(p, p);
            const ulonglong2* vr = (const ulonglong2*)vs[t];
            #pragma unroll
            for (int d4 = 0; d4 < 8; d4++) {
                const ulonglong2 vv = vr[d4];
                acc[2*d4+0] = fma2(p2, vv.x, acc[2*d4+0]);
                acc[2*d4+1] = fma2(p2, vv.y, acc[2*d4+1]);
            }
        }
    }

    if (active) {
        const float inv = 1.f / l;
        float* op = out + ((size_t)b * NQ + n) * C + h * DH;
        #pragma unroll
        for (int t = 0; t < 8; t++) {
            float a0, a1, b0, b1;
            unpack2(acc[2*t+0], a0, a1);
            unpack2(acc[2*t+1], b0, b1);
            *(float4*)(op + 4 * t) = make_float4(a0 * inv, a1 * inv, b0 * inv, b1 * inv);
        }
    }
}

/* ================================================================= */
extern "C" void kernel_launch(void* const* d_in, const int* in_sizes, int n_in,
                              void* d_out, int out_size)
{
    const int base = n_in - 26;
    const float* x = (const float*)d_in[0];
    auto in = [&](int i) { return (const float*)d_in[base + i]; };

    float *tq, *tk, *tv, *qh, *kh, *vh, *oa;
    cudaGetSymbolAddress((void**)&tq, g_tq);
    cudaGetSymbolAddress((void**)&tk, g_tk);
    cudaGetSymbolAddress((void**)&tv, g_tv);
    cudaGetSymbolAddress((void**)&qh, g_q);
    cudaGetSymbolAddress((void**)&kh, g_k);
    cudaGetSymbolAddress((void**)&vh, g_v);
    cudaGetSymbolAddress((void**)&oa, g_oa);

    dw_bn_s1<<<dim3(NQ, BATCH), C>>>(x, in(0), in(1), in(2), in(3), in(4), in(5), tq);
    dw_bn_s2<<<dim3(NKV, BATCH), C>>>(x,
                                      in(8),  in(9),  in(10), in(11), in(12), in(13),
                                      in(16), in(17), in(18), in(19), in(20), in(21),
                                      tk, tv);

    gemm2<<<dim3((NQ  + 63) / 64, 2, BATCH), 256>>>(in(6),  tq, in(7),  qh, NQ,  0);
    gemm2<<<dim3((NKV + 63) / 64, 2, BATCH), 256>>>(in(14), tk, in(15), kh, NKV, 0);
    gemm2<<<dim3((NKV + 63) / 64, 2, BATCH), 256>>>(in(22), tv, in(23), vh, NKV, 0);

    attn2<<<dim3((NQ + 255) / 256, HEADS, BATCH), 256>>>(qh, kh, vh, oa);

    gemm2<<<dim3((NQ + 63) / 64, 2, BATCH), 256>>>(in(24), oa, in(25), (float*)d_out, NQ, 1);
}

// round 8
// speedup vs baseline: 3.4050x; 2.8716x over previous
#include <cuda_runtime.h>
#include <stdint.h>
#include <math.h>

#define C        256
#define HEADS    8
#define BATCH    8
#define HH       56
#define WW       56
#define NQ       (HH*WW)    /* 3136 */
#define HK       28
#define WK       28
#define NKV      (HK*WK)    /* 784 */
#define DH       32
#define EPS_BN   1e-5f

typedef uint32_t u32;

/* ---------------- scratch (device globals) ---------------- */
__device__ float g_tq[BATCH * NQ  * C];
__device__ float g_tk[BATCH * NKV * C];
__device__ float g_tv[BATCH * NKV * C];
__device__ float g_q [BATCH * HEADS * NQ  * DH];   /* (b,h,n,d)   */
__device__ float g_k [BATCH * HEADS * NKV * DH];   /* (b,h,key,d) */
__device__ float g_vt[BATCH * C * NKV];            /* (b,h,d,key) */
__device__ float g_oa[BATCH * NQ * C];             /* (b,n,c)     */

/* hi/lo truncation split of two floats into packed bf16x2 (x0 -> low half) */
__device__ __forceinline__ void hilo2(float x0, float x1, u32& hi, u32& lo) {
    const u32 b0 = __float_as_uint(x0), b1 = __float_as_uint(x1);
    hi = __byte_perm(b0, b1, 0x7632);
    const float l0 = x0 - __uint_as_float(b0 & 0xFFFF0000u);
    const float l1 = x1 - __uint_as_float(b1 & 0xFFFF0000u);
    lo = __byte_perm(__float_as_uint(l0), __float_as_uint(l1), 0x7632);
}

/* warp mma: D(16x8,f32) += A(16x16,bf16) * B(16x8,bf16) */
__device__ __forceinline__ void mma4(float* c, const u32* a, u32 b0, u32 b1) {
    asm volatile(
        "mma.sync.aligned.m16n8k16.row.col.f32.bf16.bf16.f32 "
        "{%0,%1,%2,%3}, {%4,%5,%6,%7}, {%8,%9}, {%0,%1,%2,%3};"
        : "+f"(c[0]), "+f"(c[1]), "+f"(c[2]), "+f"(c[3])
        : "r"(a[0]), "r"(a[1]), "r"(a[2]), "r"(a[3]), "r"(b0), "r"(b1));
}

/* ======================= depthwise + BN ======================= */
__global__ void dw_bn_s1(const float* __restrict__ x,
                         const float* __restrict__ w,   const float* __restrict__ dwb,
                         const float* __restrict__ gmm, const float* __restrict__ bet,
                         const float* __restrict__ rm,  const float* __restrict__ rv,
                         float* __restrict__ out)
{
    const int n = blockIdx.x, b = blockIdx.y, c = threadIdx.x;
    const int y = n / WW, x0 = n % WW;
    const float* xb = x + (size_t)b * NQ * C + c;
    float acc = 0.f;
    #pragma unroll
    for (int dy = 0; dy < 3; dy++) {
        const int yy = y + dy - 1;
        if (yy < 0 || yy >= HH) continue;
        #pragma unroll
        for (int dx = 0; dx < 3; dx++) {
            const int xx = x0 + dx - 1;
            if (xx < 0 || xx >= WW) continue;
            acc += xb[(size_t)(yy * WW + xx) * C] * w[c * 9 + dy * 3 + dx];
        }
    }
    acc += dwb[c];
    const float s = gmm[c] * rsqrtf(rv[c] + EPS_BN);
    out[((size_t)b * NQ + n) * C + c] = acc * s + (bet[c] - rm[c] * s);
}

__global__ void dw_bn_s2(const float* __restrict__ x,
                         const float* __restrict__ kw, const float* __restrict__ kdwb,
                         const float* __restrict__ kg, const float* __restrict__ kb,
                         const float* __restrict__ km, const float* __restrict__ kvv,
                         const float* __restrict__ vw, const float* __restrict__ vdwb,
                         const float* __restrict__ vg, const float* __restrict__ vb,
                         const float* __restrict__ vm, const float* __restrict__ vvv,
                         float* __restrict__ outk, float* __restrict__ outv)
{
    const int n = blockIdx.x, b = blockIdx.y, c = threadIdx.x;
    const int yp = n / WK, xp = n % WK;
    const float* xb = x + (size_t)b * NQ * C + c;
    float ak = 0.f, av = 0.f;
    #pragma unroll
    for (int dy = 0; dy < 3; dy++) {
        const int yy = 2 * yp + dy - 1;
        if (yy < 0 || yy >= HH) continue;
        #pragma unroll
        for (int dx = 0; dx < 3; dx++) {
            const int xx = 2 * xp + dx - 1;
            if (xx < 0 || xx >= WW) continue;
            const float xv = xb[(size_t)(yy * WW + xx) * C];
            ak += xv * kw[c * 9 + dy * 3 + dx];
            av += xv * vw[c * 9 + dy * 3 + dx];
        }
    }
    ak += kdwb[c];
    av += vdwb[c];
    const float sk = kg[c] * rsqrtf(kvv[c] + EPS_BN);
    const float sv = vg[c] * rsqrtf(vvv[c] + EPS_BN);
    const size_t o = ((size_t)b * NKV + n) * C + c;
    outk[o] = ak * sk + (kb[c] - km[c] * sk);
    outv[o] = av * sv + (vb[c] - vm[c] * sv);
}

/* =================================================================
 * mma.sync GEMM, bf16 hi/lo 3-term:
 * D[o][n] = sum_c W[o][c] * Act[b][n][c] + bias[o]
 * Block 128(o) x 64(n), 256 threads = 8 warps (4 m x 2 n), warp 32x32.
 * K chunked by 32; smem rows padded to 20 u32 (conflict-free frags).
 * mode 0: (b, o>>5, n, o&31)  mode 1: (b, n, o)  mode 2: (b, o>>5, o&31, n)
 * ================================================================= */
__global__ __launch_bounds__(256) void gemm_mma(const float* __restrict__ A,
                                                const float* __restrict__ B,
                                                const float* __restrict__ bias,
                                                float* __restrict__ out,
                                                int Nsp, int mode)
{
    __shared__ u32 Ash[2][128 * 20];
    __shared__ u32 Bsh[2][64 * 20];

    const int tid = threadIdx.x, lane = tid & 31, wid = tid >> 5;
    const int g = lane >> 2, tig = lane & 3;
    const int wm = wid & 3, wn = wid >> 2;
    const int b = blockIdx.z;
    const int n0 = blockIdx.x * 64;
    const int o0 = blockIdx.y * 128;

    float acc[2][4][4];
    #pragma unroll
    for (int mt = 0; mt < 2; mt++)
        #pragma unroll
        for (int nt = 0; nt < 4; nt++)
            #pragma unroll
            for (int i = 0; i < 4; i++) acc[mt][nt][i] = 0.f;

    const int arow = tid >> 1, ak0 = (tid & 1) * 16;
    const int brow = tid >> 2, bk0 = (tid & 3) * 8;
    const bool bval = (n0 + brow) < Nsp;
    const float* Ap = A + (size_t)(o0 + arow) * C + ak0;
    const float* Bp = B + ((size_t)b * Nsp + (bval ? n0 + brow : 0)) * C + bk0;

    for (int k0 = 0; k0 < C; k0 += 32) {
        __syncthreads();
        /* fill A: 16 floats/thread -> 8 hi + 8 lo pairs */
        {
            u32* dh = &Ash[0][arow * 20 + (ak0 >> 1)];
            u32* dl = &Ash[1][arow * 20 + (ak0 >> 1)];
            #pragma unroll
            for (int t = 0; t < 4; t++) {
                const float4 v = *(const float4*)(Ap + k0 + 4 * t);
                u32 h0, l0, h1, l1;
                hilo2(v.x, v.y, h0, l0);
                hilo2(v.z, v.w, h1, l1);
                dh[2 * t] = h0; dh[2 * t + 1] = h1;
                dl[2 * t] = l0; dl[2 * t + 1] = l1;
            }
        }
        /* fill B: 8 floats/thread -> 4 hi + 4 lo pairs */
        {
            u32* dh = &Bsh[0][brow * 20 + (bk0 >> 1)];
            u32* dl = &Bsh[1][brow * 20 + (bk0 >> 1)];
            #pragma unroll
            for (int t = 0; t < 2; t++) {
                float4 v = make_float4(0.f, 0.f, 0.f, 0.f);
                if (bval) v = *(const float4*)(Bp + k0 + 4 * t);
                u32 h0, l0, h1, l1;
                hilo2(v.x, v.y, h0, l0);
                hilo2(v.z, v.w, h1, l1);
                dh[2 * t] = h0; dh[2 * t + 1] = h1;
                dl[2 * t] = l0; dl[2 * t + 1] = l1;
            }
        }
        __syncthreads();

        #pragma unroll
        for (int j = 0; j < 2; j++) {
            u32 ah[2][4], al[2][4];
            #pragma unroll
            for (int mt = 0; mt < 2; mt++)
                #pragma unroll
                for (int r = 0; r < 4; r++) {
                    const int row = wm * 32 + mt * 16 + g + 8 * (r & 1);
                    const int idx = row * 20 + j * 8 + (r >> 1) * 4 + tig;
                    ah[mt][r] = Ash[0][idx];
                    al[mt][r] = Ash[1][idx];
                }
            #pragma unroll
            for (int nt = 0; nt < 4; nt++) {
                const int rowb = wn * 32 + nt * 8 + g;
                const int idx = rowb * 20 + j * 8 + tig;
                const u32 bh0 = Bsh[0][idx], bh1 = Bsh[0][idx + 4];
                const u32 bl0 = Bsh[1][idx], bl1 = Bsh[1][idx + 4];
                #pragma unroll
                for (int mt = 0; mt < 2; mt++) {
                    mma4(acc[mt][nt], ah[mt], bh0, bh1);
                    mma4(acc[mt][nt], ah[mt], bl0, bl1);
                    mma4(acc[mt][nt], al[mt], bh0, bh1);
                }
            }
        }
    }

    /* epilogue */
    #pragma unroll
    for (int mt = 0; mt < 2; mt++)
        #pragma unroll
        for (int i = 0; i < 4; i++) {
            const int o = o0 + wm * 32 + mt * 16 + g + 8 * (i >> 1);
            const float bi = bias[o];
            #pragma unroll
            for (int nt = 0; nt < 4; nt++) {
                const int n = n0 + wn * 32 + nt * 8 + 2 * tig + (i & 1);
                if (n >= Nsp) continue;
                const float val = acc[mt][nt][i] + bi;
                if (mode == 0)
                    out[(((size_t)b * HEADS + (o >> 5)) * Nsp + n) * DH + (o & 31)] = val;
                else if (mode == 1)
                    out[((size_t)b * Nsp + n) * C + o] = val;
                else
                    out[(((size_t)b * HEADS + (o >> 5)) * DH + (o & 31)) * (size_t)NKV + n] = val;
            }
        }
}

/* =================================================================
 * mma.sync flash attention, bf16 hi/lo 3-term.
 * Block = (b, h, 128 queries), 256 threads = 8 warps (16 rows each).
 * 64-key chunks; Q in register A-frags; S in C-frags through a
 * fragment-native online softmax; P repacked in-register for PV.
 * grid (25, HEADS, BATCH)
 * ================================================================= */
__global__ __launch_bounds__(256) void attn_mma(const float* __restrict__ q,
                                                const float* __restrict__ k,
                                                const float* __restrict__ vt,
                                                float* __restrict__ out)
{
    __shared__ u32 Ksh[2][64 * 20];   /* [hi/lo][key][d pairs] pad 20 */
    __shared__ u32 Vsh[2][32 * 36];   /* [hi/lo][d][key pairs] pad 36 */

    const int tid = threadIdx.x, lane = tid & 31, wid = tid >> 5;
    const int g = lane >> 2, tig = lane & 3;
    const int b = blockIdx.z, h = blockIdx.y;
    const int m0 = blockIdx.x * 128;
    const size_t bh = (size_t)b * HEADS + h;
    const float scale = 0.17677669529663688f;

    /* Q fragments (scale folded), direct from gmem */
    u32 qh[2][4], ql[2][4];
    {
        const float* qb = q + bh * NQ * DH;
        #pragma unroll
        for (int j = 0; j < 2; j++)
            #pragma unroll
            for (int r = 0; r < 4; r++) {
                const int row = m0 + wid * 16 + g + 8 * (r & 1);
                const int kk = j * 16 + (r >> 1) * 8 + 2 * tig;
                float2 v = make_float2(0.f, 0.f);
                if (row < NQ) v = *(const float2*)(qb + (size_t)row * DH + kk);
                hilo2(v.x * scale, v.y * scale, qh[j][r], ql[j][r]);
            }
    }

    float m[2] = {-1e30f, -1e30f}, l[2] = {0.f, 0.f};
    float co[4][4];
    #pragma unroll
    for (int nt = 0; nt < 4; nt++)
        #pragma unroll
        for (int i = 0; i < 4; i++) co[nt][i] = 0.f;

    const float* kb = k  + bh * NKV * DH;
    const float* vb = vt + bh * DH * NKV;

    for (int j0 = 0; j0 < NKV; j0 += 64) {
        __syncthreads();
        /* K tile: row = key (64), 4 threads/row x 8 d */
        {
            const int row = tid >> 2, qd = (tid & 3) * 8;
            const bool kv = (j0 + row) < NKV;
            const float* p = kb + (size_t)(kv ? j0 + row : 0) * DH + qd;
            u32* dh = &Ksh[0][row * 20 + (qd >> 1)];
            u32* dl = &Ksh[1][row * 20 + (qd >> 1)];
            #pragma unroll
            for (int t = 0; t < 2; t++) {
                float4 v = make_float4(0.f, 0.f, 0.f, 0.f);
                if (kv) v = *(const float4*)(p + 4 * t);
                u32 h0, l0, h1, l1;
                hilo2(v.x, v.y, h0, l0);
                hilo2(v.z, v.w, h1, l1);
                dh[2 * t] = h0; dh[2 * t + 1] = h1;
                dl[2 * t] = l0; dl[2 * t + 1] = l1;
            }
        }
        /* Vt tile: row = d (32), 8 threads/row x 8 keys */
        {
            const int row = tid >> 3, ko = (tid & 7) * 8;
            const bool vvld = (j0 + ko) < NKV;   /* NKV % 8 == 0 */
            const float* p = vb + (size_t)row * NKV + j0 + ko;
            u32* dh = &Vsh[0][row * 36 + (ko >> 1)];
            u32* dl = &Vsh[1][row * 36 + (ko >> 1)];
            #pragma unroll
            for (int t = 0; t < 2; t++) {
                float4 v = make_float4(0.f, 0.f, 0.f, 0.f);
                if (vvld) v = *(const float4*)(p + 4 * t);
                u32 h0, l0, h1, l1;
                hilo2(v.x, v.y, h0, l0);
                hilo2(v.z, v.w, h1, l1);
                dh[2 * t] = h0; dh[2 * t + 1] = h1;
                dl[2 * t] = l0; dl[2 * t + 1] = l1;
            }
        }
        __syncthreads();

        /* ---- S = Q Kt into C-frags cs[8 keytiles][4] ---- */
        float cs[8][4];
        #pragma unroll
        for (int nt = 0; nt < 8; nt++)
            #pragma unroll
            for (int i = 0; i < 4; i++) cs[nt][i] = 0.f;
        #pragma unroll
        for (int j = 0; j < 2; j++)
            #pragma unroll
            for (int nt = 0; nt < 8; nt++) {
                const int idx = (nt * 8 + g) * 20 + j * 8 + tig;
                const u32 kh0 = Ksh[0][idx], kh1 = Ksh[0][idx + 4];
                const u32 kl0 = Ksh[1][idx], kl1 = Ksh[1][idx + 4];
                mma4(cs[nt], qh[j], kh0, kh1);
                mma4(cs[nt], qh[j], kl0, kl1);
                mma4(cs[nt], ql[j], kh0, kh1);
            }

        /* mask invalid keys (last chunk) */
        if (j0 + 64 > NKV) {
            #pragma unroll
            for (int nt = 0; nt < 8; nt++)
                #pragma unroll
                for (int i = 0; i < 4; i++) {
                    const int key = j0 + nt * 8 + 2 * tig + (i & 1);
                    if (key >= NKV) cs[nt][i] = -1e30f;
                }
        }

        /* ---- online softmax; lane owns rows g (i=0,1) and g+8 (i=2,3) ---- */
        #pragma unroll
        for (int side = 0; side < 2; side++) {
            float mx = -1e30f;
            #pragma unroll
            for (int nt = 0; nt < 8; nt++) {
                mx = fmaxf(mx, cs[nt][2 * side]);
                mx = fmaxf(mx, cs[nt][2 * side + 1]);
            }
            mx = fmaxf(mx, __shfl_xor_sync(0xffffffffu, mx, 1));
            mx = fmaxf(mx, __shfl_xor_sync(0xffffffffu, mx, 2));
            const float nm = fmaxf(m[side], mx);
            const float corr = __expf(m[side] - nm);
            m[side] = nm;
            l[side] *= corr;
            #pragma unroll
            for (int nt = 0; nt < 4; nt++) {
                co[nt][2 * side]     *= corr;
                co[nt][2 * side + 1] *= corr;
            }
            float sum = 0.f;
            #pragma unroll
            for (int nt = 0; nt < 8; nt++) {
                const float p0 = __expf(cs[nt][2 * side]     - nm);
                const float p1 = __expf(cs[nt][2 * side + 1] - nm);
                cs[nt][2 * side] = p0;
                cs[nt][2 * side + 1] = p1;
                sum += p0 + p1;
            }
            sum += __shfl_xor_sync(0xffffffffu, sum, 1);
            sum += __shfl_xor_sync(0xffffffffu, sum, 2);
            l[side] += sum;
        }

        /* ---- O += P Vt; P repacked in-register as A-frags ---- */
        #pragma unroll
        for (int t = 0; t < 4; t++) {
            u32 ph[4], pl[4];
            hilo2(cs[2 * t][0],     cs[2 * t][1],     ph[0], pl[0]);
            hilo2(cs[2 * t][2],     cs[2 * t][3],     ph[1], pl[1]);
            hilo2(cs[2 * t + 1][0], cs[2 * t + 1][1], ph[2], pl[2]);
            hilo2(cs[2 * t + 1][2], cs[2 * t + 1][3], ph[3], pl[3]);
            #pragma unroll
            for (int nt = 0; nt < 4; nt++) {
                const int idx = (nt * 8 + g) * 36 + t * 8 + tig;
                const u32 vh0 = Vsh[0][idx], vh1 = Vsh[0][idx + 4];
                const u32 vl0 = Vsh[1][idx], vl1 = Vsh[1][idx + 4];
                mma4(co[nt], ph, vh0, vh1);
                mma4(co[nt], pl, vh0, vh1);
                mma4(co[nt], ph, vl0, vl1);
            }
        }
    }

    /* ---- epilogue: out (b, n, c) ---- */
    #pragma unroll
    for (int side = 0; side < 2; side++) {
        const int row = m0 + wid * 16 + g + 8 * side;
        if (row >= NQ) continue;
        const float inv = 1.f / l[side];
        float* op = out + ((size_t)b * NQ + row) * C + h * DH;
        #pragma unroll
        for (int nt = 0; nt < 4; nt++) {
            float2 v;
            v.x = co[nt][2 * side] * inv;
            v.y = co[nt][2 * side + 1] * inv;
            *(float2*)(op + nt * 8 + 2 * tig) = v;
        }
    }
}

/* ================================================================= */
extern "C" void kernel_launch(void* const* d_in, const int* in_sizes, int n_in,
                              void* d_out, int out_size)
{
    const int base = n_in - 26;
    const float* x = (const float*)d_in[0];
    auto in = [&](int i) { return (const float*)d_in[base + i]; };

    float *tq, *tk, *tv, *qh, *kh, *vth, *oa;
    cudaGetSymbolAddress((void**)&tq,  g_tq);
    cudaGetSymbolAddress((void**)&tk,  g_tk);
    cudaGetSymbolAddress((void**)&tv,  g_tv);
    cudaGetSymbolAddress((void**)&qh,  g_q);
    cudaGetSymbolAddress((void**)&kh,  g_k);
    cudaGetSymbolAddress((void**)&vth, g_vt);
    cudaGetSymbolAddress((void**)&oa,  g_oa);

    dw_bn_s1<<<dim3(NQ, BATCH), C>>>(x, in(0), in(1), in(2), in(3), in(4), in(5), tq);
    dw_bn_s2<<<dim3(NKV, BATCH), C>>>(x,
                                      in(8),  in(9),  in(10), in(11), in(12), in(13),
                                      in(16), in(17), in(18), in(19), in(20), in(21),
                                      tk, tv);

    const int nbq  = (NQ  + 63) / 64;   /* 49 */
    const int nbkv = (NKV + 63) / 64;   /* 13 */
    gemm_mma<<<dim3(nbq,  2, BATCH), 256>>>(in(6),  tq, in(7),  qh,  NQ,  0);
    gemm_mma<<<dim3(nbkv, 2, BATCH), 256>>>(in(14), tk, in(15), kh,  NKV, 0);
    gemm_mma<<<dim3(nbkv, 2, BATCH), 256>>>(in(22), tv, in(23), vth, NKV, 2);

    attn_mma<<<dim3((NQ + 127) / 128, HEADS, BATCH), 256>>>(qh, kh, vth, oa);

    gemm_mma<<<dim3(nbq, 2, BATCH), 256>>>(in(24), oa, in(25), (float*)d_out, NQ, 1);
}

// round 10
// speedup vs baseline: 3.6697x; 1.0777x over previous
#include <cuda_runtime.h>
#include <stdint.h>
#include <math.h>

#define C        256
#define HEADS    8
#define BATCH    8
#define HH       56
#define WW       56
#define NQ       (HH*WW)    /* 3136 */
#define HK       28
#define WK       28
#define NKV      (HK*WK)    /* 784 */
#define DH       32
#define EPS_BN   1e-5f

typedef uint32_t u32;

/* ---------------- scratch (device globals) ---------------- */
__device__ float g_tq[BATCH * NQ  * C];
__device__ float g_tk[BATCH * NKV * C];
__device__ float g_tv[BATCH * NKV * C];
__device__ float g_q [BATCH * HEADS * NQ  * DH];   /* (b,h,n,d)   */
__device__ float g_k [BATCH * HEADS * NKV * DH];   /* (b,h,key,d) */
__device__ float g_vt[BATCH * C * NKV];            /* (b,h,d,key) */
__device__ float g_oa[BATCH * NQ * C];             /* (b,n,c)     */

/* hi/lo truncation split of two floats into packed bf16x2 (x0 -> low half) */
__device__ __forceinline__ void hilo2(float x0, float x1, u32& hi, u32& lo) {
    const u32 b0 = __float_as_uint(x0), b1 = __float_as_uint(x1);
    hi = __byte_perm(b0, b1, 0x7632);
    const float l0 = x0 - __uint_as_float(b0 & 0xFFFF0000u);
    const float l1 = x1 - __uint_as_float(b1 & 0xFFFF0000u);
    lo = __byte_perm(__float_as_uint(l0), __float_as_uint(l1), 0x7632);
}

__device__ __forceinline__ u32 smem_u32(const void* p) {
    u32 a;
    asm("{ .reg .u64 t; cvta.to.shared.u64 t, %1; cvt.u32.u64 %0, t; }" : "=r"(a) : "l"(p));
    return a;
}

/* warp mma: D(16x8,f32) += A(16x16,bf16) * B(16x8,bf16) */
__device__ __forceinline__ void mma4(float* c, const u32* a, u32 b0, u32 b1) {
    asm volatile(
        "mma.sync.aligned.m16n8k16.row.col.f32.bf16.bf16.f32 "
        "{%0,%1,%2,%3}, {%4,%5,%6,%7}, {%8,%9}, {%0,%1,%2,%3};"
        : "+f"(c[0]), "+f"(c[1]), "+f"(c[2]), "+f"(c[3])
        : "r"(a[0]), "r"(a[1]), "r"(a[2]), "r"(a[3]), "r"(b0), "r"(b1));
}

__device__ __forceinline__ void ldsm4(u32* r, u32 addr) {
    asm volatile("ldmatrix.sync.aligned.m8n8.x4.shared.b16 {%0,%1,%2,%3}, [%4];"
                 : "=r"(r[0]), "=r"(r[1]), "=r"(r[2]), "=r"(r[3]) : "r"(addr));
}

/* ============ depthwise + BN, sliding-window (3 loads/out) ============ */
__global__ __launch_bounds__(C) void dw_bn_s1(const float* __restrict__ x,
                         const float* __restrict__ w,   const float* __restrict__ dwb,
                         const float* __restrict__ gmm, const float* __restrict__ bet,
                         const float* __restrict__ rm,  const float* __restrict__ rv,
                         float* __restrict__ out)
{
    const int y = blockIdx.x, b = blockIdx.y, c = threadIdx.x;
    const float* xb = x + (size_t)b * NQ * C + c;
    float wr[9];
    #pragma unroll
    for (int i = 0; i < 9; i++) wr[i] = w[c * 9 + i];
    const float s  = gmm[c] * rsqrtf(rv[c] + EPS_BN);
    const float sh = bet[c] - rm[c] * s;
    const float bia = dwb[c];
    const bool t0 = y > 0, t2 = y < HH - 1;

    float am0 = 0.f, am1 = 0.f, am2 = 0.f;
    float a00 = t0 ? xb[(size_t)((y - 1) * WW) * C] : 0.f;
    float a01 =      xb[(size_t)(y * WW) * C];
    float a02 = t2 ? xb[(size_t)((y + 1) * WW) * C] : 0.f;
    float* op = out + ((size_t)b * NQ + y * WW) * C + c;

    for (int xx = 0; xx < WW; xx++) {
        float ap0 = 0.f, ap1 = 0.f, ap2 = 0.f;
        if (xx + 1 < WW) {
            ap0 = t0 ? xb[(size_t)((y - 1) * WW + xx + 1) * C] : 0.f;
            ap1 =      xb[(size_t)(y * WW + xx + 1) * C];
            ap2 = t2 ? xb[(size_t)((y + 1) * WW + xx + 1) * C] : 0.f;
        }
        float acc = bia
            + am0 * wr[0] + a00 * wr[1] + ap0 * wr[2]
            + am1 * wr[3] + a01 * wr[4] + ap1 * wr[5]
            + am2 * wr[6] + a02 * wr[7] + ap2 * wr[8];
        op[(size_t)xx * C] = acc * s + sh;
        am0 = a00; am1 = a01; am2 = a02;
        a00 = ap0; a01 = ap1; a02 = ap2;
    }
}

__global__ __launch_bounds__(C) void dw_bn_s2(const float* __restrict__ x,
                         const float* __restrict__ kw, const float* __restrict__ kdwb,
                         const float* __restrict__ kg, const float* __restrict__ kb,
                         const float* __restrict__ km, const float* __restrict__ kvv,
                         const float* __restrict__ vw, const float* __restrict__ vdwb,
                         const float* __restrict__ vg, const float* __restrict__ vb,
                         const float* __restrict__ vm, const float* __restrict__ vvv,
                         float* __restrict__ outk, float* __restrict__ outv)
{
    const int yp = blockIdx.x, b = blockIdx.y, c = threadIdx.x;
    const float* xb = x + (size_t)b * NQ * C + c;
    float wk9[9], wv9[9];
    #pragma unroll
    for (int i = 0; i < 9; i++) { wk9[i] = kw[c * 9 + i]; wv9[i] = vw[c * 9 + i]; }
    const float sk = kg[c] * rsqrtf(kvv[c] + EPS_BN);
    const float sv = vg[c] * rsqrtf(vvv[c] + EPS_BN);
    const float shk = kb[c] - km[c] * sk, shv = vb[c] - vm[c] * sv;
    const float bk = kdwb[c], bv = vdwb[c];
    const bool t0 = yp > 0;   /* row 2yp-1 valid; 2yp+1 always <= 55 */
    const int y0 = 2 * yp;

    auto ld = [&](int yy, int xx) -> float {
        return xb[(size_t)(yy * WW + xx) * C];
    };
    float cm0 = 0.f, cm1 = 0.f, cm2 = 0.f;
    float c00 = t0 ? ld(y0 - 1, 0) : 0.f;
    float c01 = ld(y0, 0);
    float c02 = ld(y0 + 1, 0);
    float cp0 = t0 ? ld(y0 - 1, 1) : 0.f;
    float cp1 = ld(y0, 1);
    float cp2 = ld(y0 + 1, 1);
    float* opk = outk + ((size_t)b * NKV + yp * WK) * C + c;
    float* opv = outv + ((size_t)b * NKV + yp * WK) * C + c;

    for (int xp = 0; xp < WK; xp++) {
        float ak = bk
            + cm0 * wk9[0] + c00 * wk9[1] + cp0 * wk9[2]
            + cm1 * wk9[3] + c01 * wk9[4] + cp1 * wk9[5]
            + cm2 * wk9[6] + c02 * wk9[7] + cp2 * wk9[8];
        float av = bv
            + cm0 * wv9[0] + c00 * wv9[1] + cp0 * wv9[2]
            + cm1 * wv9[3] + c01 * wv9[4] + cp1 * wv9[5]
            + cm2 * wv9[6] + c02 * wv9[7] + cp2 * wv9[8];
        opk[(size_t)xp * C] = ak * sk + shk;
        opv[(size_t)xp * C] = av * sv + shv;
        if (xp + 1 < WK) {
            const int xn = 2 * (xp + 1);
            cm0 = cp0; cm1 = cp1; cm2 = cp2;
            c00 = t0 ? ld(y0 - 1, xn) : 0.f;
            c01 = ld(y0, xn);
            c02 = ld(y0 + 1, xn);
            cp0 = t0 ? ld(y0 - 1, xn + 1) : 0.f;
            cp1 = ld(y0, xn + 1);
            cp2 = ld(y0 + 1, xn + 1);
        }
    }
}

/* =================================================================
 * GEMM body: D[o][n] = sum_c W[o][c] * Act[b][n][c] + bias[o]
 * 128(o) x 64(n) tile, 8 warps, ldmatrix frags, reg-staged prefetch.
 * mode 0: (b,o>>5,n,o&31)  mode 1: (b,n,o)  mode 2: (b,o>>5,o&31,n)
 * ================================================================= */
__device__ __forceinline__ void gemm_body(
    const float* __restrict__ A, const float* __restrict__ B,
    const float* __restrict__ bias, float* __restrict__ out,
    int Nsp, int mode, int n0, int o0, int b,
    u32* Ash0, u32* Ash1, u32* Bsh0, u32* Bsh1)
{
    const int tid = threadIdx.x, lane = tid & 31, wid = tid >> 5;
    const int g = lane >> 2, tig = lane & 3;
    const int wm = wid & 3, wn = wid >> 2;

    float acc[2][4][4];
    #pragma unroll
    for (int mt = 0; mt < 2; mt++)
        #pragma unroll
        for (int nt = 0; nt < 4; nt++)
            #pragma unroll
            for (int i = 0; i < 4; i++) acc[mt][nt][i] = 0.f;

    const int arow = tid >> 1, ak0 = (tid & 1) * 16;
    const int brow = tid >> 2, bk0 = (tid & 3) * 8;
    const bool bval = (n0 + brow) < Nsp;
    const float* Ap = A + (size_t)(o0 + arow) * C + ak0;
    const float* Bp = B + ((size_t)b * Nsp + (bval ? n0 + brow : 0)) * C + bk0;

    const u32 ab0 = smem_u32(Ash0), ab1 = smem_u32(Ash1);
    const u32 bb0 = smem_u32(Bsh0), bb1 = smem_u32(Bsh1);
    const u32 aoff = ((wm * 32 + ((lane >> 3) & 1) * 8 + (lane & 7)) * 20 + (lane >> 4) * 4) * 4;
    const u32 boff = ((wn * 32 + (lane >> 4) * 8 + (lane & 7)) * 20 + ((lane >> 3) & 1) * 4) * 4;

    float4 pa0 = *(const float4*)(Ap);
    float4 pa1 = *(const float4*)(Ap + 4);
    float4 pa2 = *(const float4*)(Ap + 8);
    float4 pa3 = *(const float4*)(Ap + 12);
    float4 pb0 = make_float4(0.f, 0.f, 0.f, 0.f), pb1 = pb0;
    if (bval) { pb0 = *(const float4*)(Bp); pb1 = *(const float4*)(Bp + 4); }

    for (int chunk = 0; chunk < 8; chunk++) {
        __syncthreads();
        {
            u32* dh = &Ash0[arow * 20 + (ak0 >> 1)];
            u32* dl = &Ash1[arow * 20 + (ak0 >> 1)];
            u32 h, l;
            hilo2(pa0.x, pa0.y, h, l); dh[0] = h; dl[0] = l;
            hilo2(pa0.z, pa0.w, h, l); dh[1] = h; dl[1] = l;
            hilo2(pa1.x, pa1.y, h, l); dh[2] = h; dl[2] = l;
            hilo2(pa1.z, pa1.w, h, l); dh[3] = h; dl[3] = l;
            hilo2(pa2.x, pa2.y, h, l); dh[4] = h; dl[4] = l;
            hilo2(pa2.z, pa2.w, h, l); dh[5] = h; dl[5] = l;
            hilo2(pa3.x, pa3.y, h, l); dh[6] = h; dl[6] = l;
            hilo2(pa3.z, pa3.w, h, l); dh[7] = h; dl[7] = l;
            u32* eh = &Bsh0[brow * 20 + (bk0 >> 1)];
            u32* el = &Bsh1[brow * 20 + (bk0 >> 1)];
            hilo2(pb0.x, pb0.y, h, l); eh[0] = h; el[0] = l;
            hilo2(pb0.z, pb0.w, h, l); eh[1] = h; el[1] = l;
            hilo2(pb1.x, pb1.y, h, l); eh[2] = h; el[2] = l;
            hilo2(pb1.z, pb1.w, h, l); eh[3] = h; el[3] = l;
        }
        __syncthreads();
        if (chunk < 7) {
            const int k0 = (chunk + 1) * 32;
            pa0 = *(const float4*)(Ap + k0);
            pa1 = *(const float4*)(Ap + k0 + 4);
            pa2 = *(const float4*)(Ap + k0 + 8);
            pa3 = *(const float4*)(Ap + k0 + 12);
            if (bval) {
                pb0 = *(const float4*)(Bp + k0);
                pb1 = *(const float4*)(Bp + k0 + 4);
            }
        }
        #pragma unroll
        for (int j = 0; j < 2; j++) {
            u32 ah[2][4], al[2][4];
            ldsm4(ah[0], ab0 + aoff + j * 32);
            ldsm4(ah[1], ab0 + aoff + 1280 + j * 32);
            ldsm4(al[0], ab1 + aoff + j * 32);
            ldsm4(al[1], ab1 + aoff + 1280 + j * 32);
            u32 bh[2][4], bl[2][4];
            ldsm4(bh[0], bb0 + boff + j * 32);
            ldsm4(bh[1], bb0 + boff + 1280 + j * 32);
            ldsm4(bl[0], bb1 + boff + j * 32);
            ldsm4(bl[1], bb1 + boff + 1280 + j * 32);
            #pragma unroll
            for (int p = 0; p < 2; p++)
                #pragma unroll
                for (int hf = 0; hf < 2; hf++) {
                    const int nt = p * 2 + hf;
                    const u32 h0 = bh[p][hf * 2], h1 = bh[p][hf * 2 + 1];
                    const u32 l0 = bl[p][hf * 2], l1 = bl[p][hf * 2 + 1];
                    #pragma unroll
                    for (int mt = 0; mt < 2; mt++) {
                        mma4(acc[mt][nt], ah[mt], h0, h1);
                        mma4(acc[mt][nt], ah[mt], l0, l1);
                        mma4(acc[mt][nt], al[mt], h0, h1);
                    }
                }
        }
    }

    #pragma unroll
    for (int mt = 0; mt < 2; mt++)
        #pragma unroll
        for (int i = 0; i < 4; i++) {
            const int o = o0 + wm * 32 + mt * 16 + g + 8 * (i >> 1);
            const float bi = bias[o];
            #pragma unroll
            for (int nt = 0; nt < 4; nt++) {
                const int n = n0 + wn * 32 + nt * 8 + 2 * tig + (i & 1);
                if (n >= Nsp) continue;
                const float val = acc[mt][nt][i] + bi;
                if (mode == 0)
                    out[(((size_t)b * HEADS + (o >> 5)) * Nsp + n) * DH + (o & 31)] = val;
                else if (mode == 1)
                    out[((size_t)b * Nsp + n) * C + o] = val;
                else
                    out[(((size_t)b * HEADS + (o >> 5)) * DH + (o & 31)) * (size_t)NKV + n] = val;
            }
        }
}

#define NTQ  49   /* NQ/64 */
#define NTKV 13   /* ceil(NKV/64) */

__global__ __launch_bounds__(256) void qkv_gemm(
    const float* __restrict__ Aq, const float* __restrict__ Bq, const float* __restrict__ bq, float* __restrict__ Oq,
    const float* __restrict__ Ak, const float* __restrict__ Bk, const float* __restrict__ bk, float* __restrict__ Ok,
    const float* __restrict__ Av, const float* __restrict__ Bv, const float* __restrict__ bv, float* __restrict__ Ov)
{
    __shared__ u32 Ash[2][128 * 20];
    __shared__ u32 Bsh[2][64 * 20];
    const int tx = blockIdx.x;
    const int o0 = blockIdx.y * 128, b = blockIdx.z;
    const float *A, *B, *bi; float* O;
    int Nsp, mode, n0;
    if (tx < NTQ)            { A = Aq; B = Bq; bi = bq; O = Oq; Nsp = NQ;  mode = 0; n0 = tx * 64; }
    else if (tx < NTQ + NTKV){ A = Ak; B = Bk; bi = bk; O = Ok; Nsp = NKV; mode = 0; n0 = (tx - NTQ) * 64; }
    else                     { A = Av; B = Bv; bi = bv; O = Ov; Nsp = NKV; mode = 2; n0 = (tx - NTQ - NTKV) * 64; }
    gemm_body(A, B, bi, O, Nsp, mode, n0, o0, b, Ash[0], Ash[1], Bsh[0], Bsh[1]);
}

__global__ __launch_bounds__(256) void proj_gemm(
    const float* __restrict__ A, const float* __restrict__ B,
    const float* __restrict__ bias, float* __restrict__ out)
{
    __shared__ u32 Ash[2][128 * 20];
    __shared__ u32 Bsh[2][64 * 20];
    gemm_body(A, B, bias, out, NQ, 1, blockIdx.x * 64, blockIdx.y * 128, blockIdx.z,
              Ash[0], Ash[1], Bsh[0], Bsh[1]);
}

/* =================================================================
 * mma.sync flash attention: ldmatrix frags, reg prefetch, exp2.
 * Block = (b, h, 128 queries), 256 threads = 8 warps (16 rows each).
 * ================================================================= */
__global__ __launch_bounds__(256) void attn_mma(const float* __restrict__ q,
                                                const float* __restrict__ k,
                                                const float* __restrict__ vt,
                                                float* __restrict__ out)
{
    __shared__ u32 Ksh[2][64 * 20];   /* [hi/lo][key][d pairs] pad 20 */
    __shared__ u32 Vsh[2][32 * 36];   /* [hi/lo][d][key pairs] pad 36 */

    const int tid = threadIdx.x, lane = tid & 31, wid = tid >> 5;
    const int g = lane >> 2, tig = lane & 3;
    const int b = blockIdx.z, h = blockIdx.y;
    const int m0 = blockIdx.x * 128;
    const size_t bh = (size_t)b * HEADS + h;
    /* softmax in base-2: fold log2(e) into the q scale */
    const float scale = 0.17677669529663688f * 1.44269504088896340f;

    u32 qh[2][4], ql[2][4];
    {
        const float* qb = q + bh * NQ * DH;
        #pragma unroll
        for (int j = 0; j < 2; j++)
            #pragma unroll
            for (int r = 0; r < 4; r++) {
                const int row = m0 + wid * 16 + g + 8 * (r & 1);
                const int kk = j * 16 + (r >> 1) * 8 + 2 * tig;
                float2 v = make_float2(0.f, 0.f);
                if (row < NQ) v = *(const float2*)(qb + (size_t)row * DH + kk);
                hilo2(v.x * scale, v.y * scale, qh[j][r], ql[j][r]);
            }
    }

    float m[2] = {-1e30f, -1e30f}, l[2] = {0.f, 0.f};
    float co[4][4];
    #pragma unroll
    for (int nt = 0; nt < 4; nt++)
        #pragma unroll
        for (int i = 0; i < 4; i++) co[nt][i] = 0.f;

    const float* kb = k  + bh * NKV * DH;
    const float* vb = vt + bh * DH * NKV;

    const u32 kb0 = smem_u32(Ksh[0]), kb1 = smem_u32(Ksh[1]);
    const u32 vb0 = smem_u32(Vsh[0]), vb1 = smem_u32(Vsh[1]);
    const u32 koff = (((lane >> 4) * 8 + (lane & 7)) * 20 + ((lane >> 3) & 1) * 4) * 4;
    const u32 voff = (((lane >> 4) * 8 + (lane & 7)) * 36 + ((lane >> 3) & 1) * 4) * 4;

    /* staging indices */
    const int krow = tid >> 2, kqd = (tid & 3) * 8;
    const int vrow = tid >> 3, vko = (tid & 7) * 8;

    /* prefetch chunk 0 */
    float4 ka0, ka1, va0, va1;
    {
        const bool kv = krow < NKV;
        const float* p = kb + (size_t)(kv ? krow : 0) * DH + kqd;
        ka0 = kv ? *(const float4*)(p) : make_float4(0.f, 0.f, 0.f, 0.f);
        ka1 = kv ? *(const float4*)(p + 4) : make_float4(0.f, 0.f, 0.f, 0.f);
        const bool vv = vko < NKV;
        const float* pv = vb + (size_t)vrow * NKV + vko;
        va0 = vv ? *(const float4*)(pv) : make_float4(0.f, 0.f, 0.f, 0.f);
        va1 = vv ? *(const float4*)(pv + 4) : make_float4(0.f, 0.f, 0.f, 0.f);
    }

    const int NCH = (NKV + 63) / 64;   /* 13 */
    for (int ci = 0; ci < NCH; ci++) {
        const int j0 = ci * 64;
        __syncthreads();
        {
            u32* dh = &Ksh[0][krow * 20 + (kqd >> 1)];
            u32* dl = &Ksh[1][krow * 20 + (kqd >> 1)];
            u32 hh, ll;
            hilo2(ka0.x, ka0.y, hh, ll); dh[0] = hh; dl[0] = ll;
            hilo2(ka0.z, ka0.w, hh, ll); dh[1] = hh; dl[1] = ll;
            hilo2(ka1.x, ka1.y, hh, ll); dh[2] = hh; dl[2] = ll;
            hilo2(ka1.z, ka1.w, hh, ll); dh[3] = hh; dl[3] = ll;
            u32* eh = &Vsh[0][vrow * 36 + (vko >> 1)];
            u32* el = &Vsh[1][vrow * 36 + (vko >> 1)];
            hilo2(va0.x, va0.y, hh, ll); eh[0] = hh; el[0] = ll;
            hilo2(va0.z, va0.w, hh, ll); eh[1] = hh; el[1] = ll;
            hilo2(va1.x, va1.y, hh, ll); eh[2] = hh; el[2] = ll;
            hilo2(va1.z, va1.w, hh, ll); eh[3] = hh; el[3] = ll;
        }
        __syncthreads();
        if (ci + 1 < NCH) {
            const int jn = j0 + 64;
            const bool kv = (jn + krow) < NKV;
            const float* p = kb + (size_t)(kv ? jn + krow : 0) * DH + kqd;
            ka0 = kv ? *(const float4*)(p) : make_float4(0.f, 0.f, 0.f, 0.f);
            ka1 = kv ? *(const float4*)(p + 4) : make_float4(0.f, 0.f, 0.f, 0.f);
            const bool vv = (jn + vko) < NKV;
            const float* pv = vb + (size_t)vrow * NKV + jn + vko;
            va0 = vv ? *(const float4*)(pv) : make_float4(0.f, 0.f, 0.f, 0.f);
            va1 = vv ? *(const float4*)(pv + 4) : make_float4(0.f, 0.f, 0.f, 0.f);
        }

        /* ---- S = Q Kt ---- */
        float cs[8][4];
        #pragma unroll
        for (int nt = 0; nt < 8; nt++)
            #pragma unroll
            for (int i = 0; i < 4; i++) cs[nt][i] = 0.f;
        #pragma unroll
        for (int j = 0; j < 2; j++)
            #pragma unroll
            for (int p = 0; p < 4; p++) {
                u32 rh[4], rl[4];
                ldsm4(rh, kb0 + koff + p * 1280 + j * 32);
                ldsm4(rl, kb1 + koff + p * 1280 + j * 32);
                mma4(cs[2 * p],     qh[j], rh[0], rh[1]);
                mma4(cs[2 * p],     qh[j], rl[0], rl[1]);
                mma4(cs[2 * p],     ql[j], rh[0], rh[1]);
                mma4(cs[2 * p + 1], qh[j], rh[2], rh[3]);
                mma4(cs[2 * p + 1], qh[j], rl[2], rl[3]);
                mma4(cs[2 * p + 1], ql[j], rh[2], rh[3]);
            }

        if (j0 + 64 > NKV) {
            #pragma unroll
            for (int nt = 0; nt < 8; nt++)
                #pragma unroll
                for (int i = 0; i < 4; i++) {
                    const int key = j0 + nt * 8 + 2 * tig + (i & 1);
                    if (key >= NKV) cs[nt][i] = -1e30f;
                }
        }

        /* ---- online softmax (base 2) ---- */
        #pragma unroll
        for (int side = 0; side < 2; side++) {
            float mx = -1e30f;
            #pragma unroll
            for (int nt = 0; nt < 8; nt++) {
                mx = fmaxf(mx, cs[nt][2 * side]);
                mx = fmaxf(mx, cs[nt][2 * side + 1]);
            }
            mx = fmaxf(mx, __shfl_xor_sync(0xffffffffu, mx, 1));
            mx = fmaxf(mx, __shfl_xor_sync(0xffffffffu, mx, 2));
            const float nm = fmaxf(m[side], mx);
            const float corr = exp2f(m[side] - nm);
            m[side] = nm;
            l[side] *= corr;
            #pragma unroll
            for (int nt = 0; nt < 4; nt++) {
                co[nt][2 * side]     *= corr;
                co[nt][2 * side + 1] *= corr;
            }
            float sum = 0.f;
            #pragma unroll
            for (int nt = 0; nt < 8; nt++) {
                const float p0 = exp2f(cs[nt][2 * side]     - nm);
                const float p1 = exp2f(cs[nt][2 * side + 1] - nm);
                cs[nt][2 * side] = p0;
                cs[nt][2 * side + 1] = p1;
                sum += p0 + p1;
            }
            sum += __shfl_xor_sync(0xffffffffu, sum, 1);
            sum += __shfl_xor_sync(0xffffffffu, sum, 2);
            l[side] += sum;
        }

        /* ---- O += P Vt ---- */
        #pragma unroll
        for (int t = 0; t < 4; t++) {
            u32 ph[4], pl[4];
            hilo2(cs[2 * t][0],     cs[2 * t][1],     ph[0], pl[0]);
            hilo2(cs[2 * t][2],     cs[2 * t][3],     ph[1], pl[1]);
            hilo2(cs[2 * t + 1][0], cs[2 * t + 1][1], ph[2], pl[2]);
            hilo2(cs[2 * t + 1][2], cs[2 * t + 1][3], ph[3], pl[3]);
            #pragma unroll
            for (int p = 0; p < 2; p++) {
                u32 vh[4], vl[4];
                ldsm4(vh, vb0 + voff + p * 2304 + t * 32);
                ldsm4(vl, vb1 + voff + p * 2304 + t * 32);
                mma4(co[2 * p],     ph, vh[0], vh[1]);
                mma4(co[2 * p],     pl, vh[0], vh[1]);
                mma4(co[2 * p],     ph, vl[0], vl[1]);
                mma4(co[2 * p + 1], ph, vh[2], vh[3]);
                mma4(co[2 * p + 1], pl, vh[2], vh[3]);
                mma4(co[2 * p + 1], ph, vl[2], vl[3]);
            }
        }
    }

    /* ---- epilogue: out (b, n, c) ---- */
    #pragma unroll
    for (int side = 0; side < 2; side++) {
        const int row = m0 + wid * 16 + g + 8 * side;
        if (row >= NQ) continue;
        const float inv = 1.f / l[side];
        float* op = out + ((size_t)b * NQ + row) * C + h * DH;
        #pragma unroll
        for (int nt = 0; nt < 4; nt++) {
            float2 v;
            v.x = co[nt][2 * side] * inv;
            v.y = co[nt][2 * side + 1] * inv;
            *(float2*)(op + nt * 8 + 2 * tig) = v;
        }
    }
}

/* ================================================================= */
extern "C" void kernel_launch(void* const* d_in, const int* in_sizes, int n_in,
                              void* d_out, int out_size)
{
    const int base = n_in - 26;
    const float* x = (const float*)d_in[0];
    auto in = [&](int i) { return (const float*)d_in[base + i]; };

    float *tq, *tk, *tv, *qh, *kh, *vth, *oa;
    cudaGetSymbolAddress((void**)&tq,  g_tq);
    cudaGetSymbolAddress((void**)&tk,  g_tk);
    cudaGetSymbolAddress((void**)&tv,  g_tv);
    cudaGetSymbolAddress((void**)&qh,  g_q);
    cudaGetSymbolAddress((void**)&kh,  g_k);
    cudaGetSymbolAddress((void**)&vth, g_vt);
    cudaGetSymbolAddress((void**)&oa,  g_oa);

    dw_bn_s1<<<dim3(HH, BATCH), C>>>(x, in(0), in(1), in(2), in(3), in(4), in(5), tq);
    dw_bn_s2<<<dim3(HK, BATCH), C>>>(x,
                                     in(8),  in(9),  in(10), in(11), in(12), in(13),
                                     in(16), in(17), in(18), in(19), in(20), in(21),
                                     tk, tv);

    qkv_gemm<<<dim3(NTQ + 2 * NTKV, 2, BATCH), 256>>>(
        in(6),  tq, in(7),  qh,
        in(14), tk, in(15), kh,
        in(22), tv, in(23), vth);

    attn_mma<<<dim3((NQ + 127) / 128, HEADS, BATCH), 256>>>(qh, kh, vth, oa);

    proj_gemm<<<dim3(NTQ, 2, BATCH), 256>>>(in(24), oa, in(25), (float*)d_out);
}

// round 15
// speedup vs baseline: 3.7372x; 1.0184x over previous
#include <cuda_runtime.h>
#include <stdint.h>
#include <math.h>

#define C        256
#define HEADS    8
#define BATCH    8
#define HH       56
#define WW       56
#define NQ       (HH*WW)    /* 3136 */
#define HK       28
#define WK       28
#define NKV      (HK*WK)    /* 784 */
#define KP       832        /* NKV padded to 13*64 */
#define DH       32
#define EPS_BN   1e-5f

typedef uint32_t u32;

/* ---------------- scratch (device globals) ---------------- */
__device__ float g_tq[BATCH * NQ  * C];
__device__ float g_tk[BATCH * NKV * C];
__device__ float g_tv[BATCH * NKV * C];
__device__ float g_q [BATCH * HEADS * NQ  * DH];   /* (b,h,n,d) f32   */
__device__ float g_k [BATCH * HEADS * NKV * DH];   /* (b,h,key,d) f32 */
__device__ u32   g_kph[BATCH * HEADS * KP * 16];   /* K hi bf16x2 (d-pairs) */
__device__ u32   g_kpl[BATCH * HEADS * KP * 16];   /* K lo */
__device__ u32   g_vph[BATCH * HEADS * DH * (KP/2)]; /* Vt hi bf16x2 (key-pairs) */
__device__ u32   g_vpl[BATCH * HEADS * DH * (KP/2)]; /* Vt lo */
__device__ float g_oa[BATCH * NQ * C];             /* (b,n,c) */

/* hi/lo truncation split of two floats into packed bf16x2 (x0 -> low half) */
__device__ __forceinline__ void hilo2(float x0, float x1, u32& hi, u32& lo) {
    const u32 b0 = __float_as_uint(x0), b1 = __float_as_uint(x1);
    hi = __byte_perm(b0, b1, 0x7632);
    const float l0 = x0 - __uint_as_float(b0 & 0xFFFF0000u);
    const float l1 = x1 - __uint_as_float(b1 & 0xFFFF0000u);
    lo = __byte_perm(__float_as_uint(l0), __float_as_uint(l1), 0x7632);
}

__device__ __forceinline__ u32 smem_u32(const void* p) {
    u32 a;
    asm("{ .reg .u64 t; cvta.to.shared.u64 t, %1; cvt.u32.u64 %0, t; }" : "=r"(a) : "l"(p));
    return a;
}

__device__ __forceinline__ void mma4(float* c, const u32* a, u32 b0, u32 b1) {
    asm volatile(
        "mma.sync.aligned.m16n8k16.row.col.f32.bf16.bf16.f32 "
        "{%0,%1,%2,%3}, {%4,%5,%6,%7}, {%8,%9}, {%0,%1,%2,%3};"
        : "+f"(c[0]), "+f"(c[1]), "+f"(c[2]), "+f"(c[3])
        : "r"(a[0]), "r"(a[1]), "r"(a[2]), "r"(a[3]), "r"(b0), "r"(b1));
}
__device__ __forceinline__ void ldsm4(u32* r, u32 addr) {
    asm volatile("ldmatrix.sync.aligned.m8n8.x4.shared.b16 {%0,%1,%2,%3}, [%4];"
                 : "=r"(r[0]), "=r"(r[1]), "=r"(r[2]), "=r"(r[3]) : "r"(addr));
}
#define CP16(dst, src) asm volatile("cp.async.cg.shared.global [%0], [%1], 16;" :: "r"(dst), "l"(src))
#define CPCOMMIT()     asm volatile("cp.async.commit_group;" ::: "memory")
#define CPWAIT(n)      asm volatile("cp.async.wait_group %0;" :: "n"(n) : "memory")

/* ============ depthwise + BN, sliding-window ============ */
__global__ __launch_bounds__(C) void dw_bn_s1(const float* __restrict__ x,
                         const float* __restrict__ w,   const float* __restrict__ dwb,
                         const float* __restrict__ gmm, const float* __restrict__ bet,
                         const float* __restrict__ rm,  const float* __restrict__ rv,
                         float* __restrict__ out)
{
    const int y = blockIdx.x, b = blockIdx.y, c = threadIdx.x;
    const float* xb = x + (size_t)b * NQ * C + c;
    float wr[9];
    #pragma unroll
    for (int i = 0; i < 9; i++) wr[i] = w[c * 9 + i];
    const float s  = gmm[c] * rsqrtf(rv[c] + EPS_BN);
    const float sh = bet[c] - rm[c] * s;
    const float bia = dwb[c];
    const bool t0 = y > 0, t2 = y < HH - 1;

    float am0 = 0.f, am1 = 0.f, am2 = 0.f;
    float a00 = t0 ? xb[(size_t)((y - 1) * WW) * C] : 0.f;
    float a01 =      xb[(size_t)(y * WW) * C];
    float a02 = t2 ? xb[(size_t)((y + 1) * WW) * C] : 0.f;
    float* op = out + ((size_t)b * NQ + y * WW) * C + c;

    for (int xx = 0; xx < WW; xx++) {
        float ap0 = 0.f, ap1 = 0.f, ap2 = 0.f;
        if (xx + 1 < WW) {
            ap0 = t0 ? xb[(size_t)((y - 1) * WW + xx + 1) * C] : 0.f;
            ap1 =      xb[(size_t)(y * WW + xx + 1) * C];
            ap2 = t2 ? xb[(size_t)((y + 1) * WW + xx + 1) * C] : 0.f;
        }
        float acc = bia
            + am0 * wr[0] + a00 * wr[1] + ap0 * wr[2]
            + am1 * wr[3] + a01 * wr[4] + ap1 * wr[5]
            + am2 * wr[6] + a02 * wr[7] + ap2 * wr[8];
        op[(size_t)xx * C] = acc * s + sh;
        am0 = a00; am1 = a01; am2 = a02;
        a00 = ap0; a01 = ap1; a02 = ap2;
    }
}

__global__ __launch_bounds__(C) void dw_bn_s2(const float* __restrict__ x,
                         const float* __restrict__ kw, const float* __restrict__ kdwb,
                         const float* __restrict__ kg, const float* __restrict__ kb,
                         const float* __restrict__ km, const float* __restrict__ kvv,
                         const float* __restrict__ vw, const float* __restrict__ vdwb,
                         const float* __restrict__ vg, const float* __restrict__ vb,
                         const float* __restrict__ vm, const float* __restrict__ vvv,
                         float* __restrict__ outk, float* __restrict__ outv)
{
    const int yp = blockIdx.x, b = blockIdx.y, c = threadIdx.x;
    const float* xb = x + (size_t)b * NQ * C + c;
    float wk9[9], wv9[9];
    #pragma unroll
    for (int i = 0; i < 9; i++) { wk9[i] = kw[c * 9 + i]; wv9[i] = vw[c * 9 + i]; }
    const float sk = kg[c] * rsqrtf(kvv[c] + EPS_BN);
    const float sv = vg[c] * rsqrtf(vvv[c] + EPS_BN);
    const float shk = kb[c] - km[c] * sk, shv = vb[c] - vm[c] * sv;
    const float bk = kdwb[c], bv = vdwb[c];
    const bool t0 = yp > 0;
    const int y0 = 2 * yp;

    auto ld = [&](int yy, int xx) -> float {
        return xb[(size_t)(yy * WW + xx) * C];
    };
    float cm0 = 0.f, cm1 = 0.f, cm2 = 0.f;
    float c00 = t0 ? ld(y0 - 1, 0) : 0.f;
    float c01 = ld(y0, 0);
    float c02 = ld(y0 + 1, 0);
    float cp0 = t0 ? ld(y0 - 1, 1) : 0.f;
    float cp1 = ld(y0, 1);
    float cp2 = ld(y0 + 1, 1);
    float* opk = outk + ((size_t)b * NKV + yp * WK) * C + c;
    float* opv = outv + ((size_t)b * NKV + yp * WK) * C + c;

    for (int xp = 0; xp < WK; xp++) {
        float ak = bk
            + cm0 * wk9[0] + c00 * wk9[1] + cp0 * wk9[2]
            + cm1 * wk9[3] + c01 * wk9[4] + cp1 * wk9[5]
            + cm2 * wk9[6] + c02 * wk9[7] + cp2 * wk9[8];
        float av = bv
            + cm0 * wv9[0] + c00 * wv9[1] + cp0 * wv9[2]
            + cm1 * wv9[3] + c01 * wv9[4] + cp1 * wv9[5]
            + cm2 * wv9[6] + c02 * wv9[7] + cp2 * wv9[8];
        opk[(size_t)xp * C] = ak * sk + shk;
        opv[(size_t)xp * C] = av * sv + shv;
        if (xp + 1 < WK) {
            const int xn = 2 * (xp + 1);
            cm0 = cp0; cm1 = cp1; cm2 = cp2;
            c00 = t0 ? ld(y0 - 1, xn) : 0.f;
            c01 = ld(y0, xn);
            c02 = ld(y0 + 1, xn);
            cp0 = t0 ? ld(y0 - 1, xn + 1) : 0.f;
            cp1 = ld(y0, xn + 1);
            cp2 = ld(y0 + 1, xn + 1);
        }
    }
}

/* ============ K pack + pad-zero for V planes ============ */
__global__ __launch_bounds__(256) void pack_k(const float* __restrict__ k,
                                              u32* __restrict__ kph, u32* __restrict__ kpl,
                                              u32* __restrict__ vph, u32* __restrict__ vpl)
{
    const int b = blockIdx.z, h = blockIdx.y;
    const size_t bh = (size_t)b * HEADS + h;
    const int tid = threadIdx.x;
    const int key = blockIdx.x * 64 + (tid >> 2);
    const int part = tid & 3;
    float4 v0 = make_float4(0.f, 0.f, 0.f, 0.f), v1 = v0;
    if (key < NKV) {
        const float* p = k + (bh * NKV + key) * DH + part * 8;
        v0 = *(const float4*)p;
        v1 = *(const float4*)(p + 4);
    }
    u32 h0, l0, h1, l1, h2, l2, h3, l3;
    hilo2(v0.x, v0.y, h0, l0);
    hilo2(v0.z, v0.w, h1, l1);
    hilo2(v1.x, v1.y, h2, l2);
    hilo2(v1.z, v1.w, h3, l3);
    const size_t o = (bh * KP + key) * 16 + part * 4;
    *(uint4*)(kph + o) = make_uint4(h0, h1, h2, h3);
    *(uint4*)(kpl + o) = make_uint4(l0, l1, l2, l3);
    /* zero the V padded tails (key pairs 392..415) once */
    if (blockIdx.x == 12) {
        for (int i = tid; i < DH * 24; i += 256) {
            const int d = i / 24, pr = NKV / 2 + i % 24;
            vph[(bh * DH + d) * (KP / 2) + pr] = 0u;
            vpl[(bh * DH + d) * (KP / 2) + pr] = 0u;
        }
    }
}

/* =================================================================
 * GEMM body (ldmatrix + reg prefetch), modes:
 * 0: f32 (b,o>>5,n,o&31)  1: f32 (b,n,o)  2: packed u32 Vt hi+lo planes
 * ================================================================= */
__device__ __forceinline__ void gemm_body(
    const float* __restrict__ A, const float* __restrict__ B,
    const float* __restrict__ bias, float* __restrict__ out,
    u32* __restrict__ outph, u32* __restrict__ outpl,
    int Nsp, int mode, int n0, int o0, int b,
    u32* Ash0, u32* Ash1, u32* Bsh0, u32* Bsh1)
{
    const int tid = threadIdx.x, lane = tid & 31, wid = tid >> 5;
    const int g = lane >> 2, tig = lane & 3;
    const int wm = wid & 3, wn = wid >> 2;

    float acc[2][4][4];
    #pragma unroll
    for (int mt = 0; mt < 2; mt++)
        #pragma unroll
        for (int nt = 0; nt < 4; nt++)
            #pragma unroll
            for (int i = 0; i < 4; i++) acc[mt][nt][i] = 0.f;

    const int arow = tid >> 1, ak0 = (tid & 1) * 16;
    const int brow = tid >> 2, bk0 = (tid & 3) * 8;
    const bool bval = (n0 + brow) < Nsp;
    const float* Ap = A + (size_t)(o0 + arow) * C + ak0;
    const float* Bp = B + ((size_t)b * Nsp + (bval ? n0 + brow : 0)) * C + bk0;

    const u32 ab0 = smem_u32(Ash0), ab1 = smem_u32(Ash1);
    const u32 bb0 = smem_u32(Bsh0), bb1 = smem_u32(Bsh1);
    const u32 aoff = ((wm * 32 + ((lane >> 3) & 1) * 8 + (lane & 7)) * 20 + (lane >> 4) * 4) * 4;
    const u32 boff = ((wn * 32 + (lane >> 4) * 8 + (lane & 7)) * 20 + ((lane >> 3) & 1) * 4) * 4;

    float4 pa0 = *(const float4*)(Ap);
    float4 pa1 = *(const float4*)(Ap + 4);
    float4 pa2 = *(const float4*)(Ap + 8);
    float4 pa3 = *(const float4*)(Ap + 12);
    float4 pb0 = make_float4(0.f, 0.f, 0.f, 0.f), pb1 = pb0;
    if (bval) { pb0 = *(const float4*)(Bp); pb1 = *(const float4*)(Bp + 4); }

    for (int chunk = 0; chunk < 8; chunk++) {
        __syncthreads();
        {
            u32* dh = &Ash0[arow * 20 + (ak0 >> 1)];
            u32* dl = &Ash1[arow * 20 + (ak0 >> 1)];
            u32 h, l;
            hilo2(pa0.x, pa0.y, h, l); dh[0] = h; dl[0] = l;
            hilo2(pa0.z, pa0.w, h, l); dh[1] = h; dl[1] = l;
            hilo2(pa1.x, pa1.y, h, l); dh[2] = h; dl[2] = l;
            hilo2(pa1.z, pa1.w, h, l); dh[3] = h; dl[3] = l;
            hilo2(pa2.x, pa2.y, h, l); dh[4] = h; dl[4] = l;
            hilo2(pa2.z, pa2.w, h, l); dh[5] = h; dl[5] = l;
            hilo2(pa3.x, pa3.y, h, l); dh[6] = h; dl[6] = l;
            hilo2(pa3.z, pa3.w, h, l); dh[7] = h; dl[7] = l;
            u32* eh = &Bsh0[brow * 20 + (bk0 >> 1)];
            u32* el = &Bsh1[brow * 20 + (bk0 >> 1)];
            hilo2(pb0.x, pb0.y, h, l); eh[0] = h; el[0] = l;
            hilo2(pb0.z, pb0.w, h, l); eh[1] = h; el[1] = l;
            hilo2(pb1.x, pb1.y, h, l); eh[2] = h; el[2] = l;
            hilo2(pb1.z, pb1.w, h, l); eh[3] = h; el[3] = l;
        }
        __syncthreads();
        if (chunk < 7) {
            const int k0 = (chunk + 1) * 32;
            pa0 = *(const float4*)(Ap + k0);
            pa1 = *(const float4*)(Ap + k0 + 4);
            pa2 = *(const float4*)(Ap + k0 + 8);
            pa3 = *(const float4*)(Ap + k0 + 12);
            if (bval) {
                pb0 = *(const float4*)(Bp + k0);
                pb1 = *(const float4*)(Bp + k0 + 4);
            }
        }
        #pragma unroll
        for (int j = 0; j < 2; j++) {
            u32 ah[2][4], al[2][4];
            ldsm4(ah[0], ab0 + aoff + j * 32);
            ldsm4(ah[1], ab0 + aoff + 1280 + j * 32);
            ldsm4(al[0], ab1 + aoff + j * 32);
            ldsm4(al[1], ab1 + aoff + 1280 + j * 32);
            u32 bh[2][4], bl[2][4];
            ldsm4(bh[0], bb0 + boff + j * 32);
            ldsm4(bh[1], bb0 + boff + 1280 + j * 32);
            ldsm4(bl[0], bb1 + boff + j * 32);
            ldsm4(bl[1], bb1 + boff + 1280 + j * 32);
            #pragma unroll
            for (int p = 0; p < 2; p++)
                #pragma unroll
                for (int hf = 0; hf < 2; hf++) {
                    const int nt = p * 2 + hf;
                    const u32 h0 = bh[p][hf * 2], h1 = bh[p][hf * 2 + 1];
                    const u32 l0 = bl[p][hf * 2], l1 = bl[p][hf * 2 + 1];
                    #pragma unroll
                    for (int mt = 0; mt < 2; mt++) {
                        mma4(acc[mt][nt], ah[mt], h0, h1);
                        mma4(acc[mt][nt], ah[mt], l0, l1);
                        mma4(acc[mt][nt], al[mt], h0, h1);
                    }
                }
        }
    }

    if (mode == 2) {
        /* write Vt hi+lo planes: (b,h,d, keypair), stride KP/2 */
        #pragma unroll
        for (int mt = 0; mt < 2; mt++)
            #pragma unroll
            for (int s = 0; s < 2; s++) {
                const int o = o0 + wm * 32 + mt * 16 + g + 8 * s;
                const float bi = bias[o];
                const int h = o >> 5, dd = o & 31;
                const size_t rowo = ((size_t)b * HEADS + h) * DH * (KP / 2) + (size_t)dd * (KP / 2);
                #pragma unroll
                for (int nt = 0; nt < 4; nt++) {
                    const int n = n0 + wn * 32 + nt * 8 + 2 * tig;
                    if (n < Nsp) {
                        u32 hv, lv;
                        hilo2(acc[mt][nt][2 * s] + bi, acc[mt][nt][2 * s + 1] + bi, hv, lv);
                        outph[rowo + (n >> 1)] = hv;
                        outpl[rowo + (n >> 1)] = lv;
                    }
                }
            }
        return;
    }
    #pragma unroll
    for (int mt = 0; mt < 2; mt++)
        #pragma unroll
        for (int i = 0; i < 4; i++) {
            const int o = o0 + wm * 32 + mt * 16 + g + 8 * (i >> 1);
            const float bi = bias[o];
            #pragma unroll
            for (int nt = 0; nt < 4; nt++) {
                const int n = n0 + wn * 32 + nt * 8 + 2 * tig + (i & 1);
                if (n >= Nsp) continue;
                const float val = acc[mt][nt][i] + bi;
                if (mode == 0)
                    out[(((size_t)b * HEADS + (o >> 5)) * Nsp + n) * DH + (o & 31)] = val;
                else
                    out[((size_t)b * Nsp + n) * C + o] = val;
            }
        }
}

#define NTQ  49   /* NQ/64 */
#define NTKV 13   /* ceil(NKV/64) */

__global__ __launch_bounds__(256) void qkv_gemm(
    const float* __restrict__ Aq, const float* __restrict__ Bq, const float* __restrict__ bq, float* __restrict__ Oq,
    const float* __restrict__ Ak, const float* __restrict__ Bk, const float* __restrict__ bk, float* __restrict__ Ok,
    const float* __restrict__ Av, const float* __restrict__ Bv, const float* __restrict__ bv,
    u32* __restrict__ Ovh, u32* __restrict__ Ovl)
{
    __shared__ u32 Ash[2][128 * 20];
    __shared__ u32 Bsh[2][64 * 20];
    const int tx = blockIdx.x;
    const int o0 = blockIdx.y * 128, b = blockIdx.z;
    const float *A, *B, *bi;
    float* O = 0; u32 *Oph = 0, *Opl = 0;
    int Nsp, mode, n0;
    if (tx < NTQ)            { A = Aq; B = Bq; bi = bq; O = Oq; Nsp = NQ;  mode = 0; n0 = tx * 64; }
    else if (tx < NTQ + NTKV){ A = Ak; B = Bk; bi = bk; O = Ok; Nsp = NKV; mode = 0; n0 = (tx - NTQ) * 64; }
    else                     { A = Av; B = Bv; bi = bv; Oph = Ovh; Opl = Ovl; Nsp = NKV; mode = 2; n0 = (tx - NTQ - NTKV) * 64; }
    gemm_body(A, B, bi, O, Oph, Opl, Nsp, mode, n0, o0, b, Ash[0], Ash[1], Bsh[0], Bsh[1]);
}

__global__ __launch_bounds__(256) void proj_gemm(
    const float* __restrict__ A, const float* __restrict__ B,
    const float* __restrict__ bias, float* __restrict__ out)
{
    __shared__ u32 Ash[2][128 * 20];
    __shared__ u32 Bsh[2][64 * 20];
    gemm_body(A, B, bias, out, 0, 0, NQ, 1, blockIdx.x * 64, blockIdx.y * 128, blockIdx.z,
              Ash[0], Ash[1], Bsh[0], Bsh[1]);
}

/* =================================================================
 * flash attention: pre-packed bf16 K(hi/lo)/V(hi/lo), cp.async 2-stage,
 * QK 3-term, PV 3-term (Ph*Vh, Pl*Vh, Ph*Vl). 128 queries/block.
 * ================================================================= */
__global__ __launch_bounds__(256) void attn_mma(const float* __restrict__ q,
                                                const u32* __restrict__ kph,
                                                const u32* __restrict__ kpl,
                                                const u32* __restrict__ vph,
                                                const u32* __restrict__ vpl,
                                                float* __restrict__ out)
{
    __shared__ u32 Ksh[2][2][64 * 20];   /* [stage][hi/lo][key][d pairs] */
    __shared__ u32 Vsh[2][2][32 * 36];   /* [stage][hi/lo][d][key pairs] */

    const int tid = threadIdx.x, lane = tid & 31, wid = tid >> 5;
    const int g = lane >> 2, tig = lane & 3;
    const int b = blockIdx.z, h = blockIdx.y;
    const int m0 = blockIdx.x * 128;
    const size_t bh = (size_t)b * HEADS + h;
    const float scale = 0.17677669529663688f * 1.44269504088896340f;

    u32 qh[2][4], ql[2][4];
    {
        const float* qb = q + bh * NQ * DH;
        #pragma unroll
        for (int j = 0; j < 2; j++)
            #pragma unroll
            for (int r = 0; r < 4; r++) {
                const int row = m0 + wid * 16 + g + 8 * (r & 1);
                const int kk = j * 16 + (r >> 1) * 8 + 2 * tig;
                float2 v = make_float2(0.f, 0.f);
                if (row < NQ) v = *(const float2*)(qb + (size_t)row * DH + kk);
                hilo2(v.x * scale, v.y * scale, qh[j][r], ql[j][r]);
            }
    }

    float m[2] = {-1e30f, -1e30f}, l[2] = {0.f, 0.f};
    float co[4][4];
    #pragma unroll
    for (int nt = 0; nt < 4; nt++)
        #pragma unroll
        for (int i = 0; i < 4; i++) co[nt][i] = 0.f;

    const u32* kphb = kph + bh * KP * 16;
    const u32* kplb = kpl + bh * KP * 16;
    const u32* vphb = vph + bh * DH * (KP / 2);
    const u32* vplb = vpl + bh * DH * (KP / 2);

    const u32 ksb[2][2] = { { smem_u32(Ksh[0][0]), smem_u32(Ksh[0][1]) },
                            { smem_u32(Ksh[1][0]), smem_u32(Ksh[1][1]) } };
    const u32 vsb[2][2] = { { smem_u32(Vsh[0][0]), smem_u32(Vsh[0][1]) },
                            { smem_u32(Vsh[1][0]), smem_u32(Vsh[1][1]) } };
    const u32 koff = (((lane >> 4) * 8 + (lane & 7)) * 20 + ((lane >> 3) & 1) * 4) * 4;
    const u32 voff = (((lane >> 4) * 8 + (lane & 7)) * 36 + ((lane >> 3) & 1) * 4) * 4;

    /* staging: K hi/lo (row=tid>>2, part=tid&3); V hi/lo (row=tid>>3, chk=tid&7) */
    const int krow = tid >> 2, kpart = tid & 3;
    const int vrow = tid >> 3, vchk = tid & 7;
    const u32 kdst = (krow * 20 + kpart * 4) * 4;
    const u32 vdst = (vrow * 36 + vchk * 4) * 4;

    auto issue = [&](int st, int j0) {
        CP16(ksb[st][0] + kdst, kphb + ((size_t)(j0 + krow)) * 16 + kpart * 4);
        CP16(ksb[st][1] + kdst, kplb + ((size_t)(j0 + krow)) * 16 + kpart * 4);
        CP16(vsb[st][0] + vdst, vphb + (size_t)vrow * (KP / 2) + (j0 >> 1) + vchk * 4);
        CP16(vsb[st][1] + vdst, vplb + (size_t)vrow * (KP / 2) + (j0 >> 1) + vchk * 4);
    };

    issue(0, 0);
    CPCOMMIT();

    const int NCH = KP / 64;   /* 13 */
    for (int ci = 0; ci < NCH; ci++) {
        const int j0 = ci * 64;
        const int st = ci & 1;
        if (ci + 1 < NCH) { issue((ci + 1) & 1, j0 + 64); CPCOMMIT(); CPWAIT(1); }
        else              { CPWAIT(0); }
        __syncthreads();

        /* ---- S = Q Kt (3-term) ---- */
        float cs[8][4];
        #pragma unroll
        for (int nt = 0; nt < 8; nt++)
            #pragma unroll
            for (int i = 0; i < 4; i++) cs[nt][i] = 0.f;
        #pragma unroll
        for (int j = 0; j < 2; j++)
            #pragma unroll
            for (int p = 0; p < 4; p++) {
                u32 rh[4], rl[4];
                ldsm4(rh, ksb[st][0] + koff + p * 1280 + j * 32);
                ldsm4(rl, ksb[st][1] + koff + p * 1280 + j * 32);
                mma4(cs[2 * p],     qh[j], rh[0], rh[1]);
                mma4(cs[2 * p],     qh[j], rl[0], rl[1]);
                mma4(cs[2 * p],     ql[j], rh[0], rh[1]);
                mma4(cs[2 * p + 1], qh[j], rh[2], rh[3]);
                mma4(cs[2 * p + 1], qh[j], rl[2], rl[3]);
                mma4(cs[2 * p + 1], ql[j], rh[2], rh[3]);
            }

        if (j0 + 64 > NKV) {
            #pragma unroll
            for (int nt = 0; nt < 8; nt++)
                #pragma unroll
                for (int i = 0; i < 4; i++) {
                    const int key = j0 + nt * 8 + 2 * tig + (i & 1);
                    if (key >= NKV) cs[nt][i] = -1e30f;
                }
        }

        /* ---- online softmax (base 2) ---- */
        #pragma unroll
        for (int side = 0; side < 2; side++) {
            float mx = -1e30f;
            #pragma unroll
            for (int nt = 0; nt < 8; nt++) {
                mx = fmaxf(mx, cs[nt][2 * side]);
                mx = fmaxf(mx, cs[nt][2 * side + 1]);
            }
            mx = fmaxf(mx, __shfl_xor_sync(0xffffffffu, mx, 1));
            mx = fmaxf(mx, __shfl_xor_sync(0xffffffffu, mx, 2));
            const float nm = fmaxf(m[side], mx);
            const float corr = exp2f(m[side] - nm);
            m[side] = nm;
            l[side] *= corr;
            #pragma unroll
            for (int nt = 0; nt < 4; nt++) {
                co[nt][2 * side]     *= corr;
                co[nt][2 * side + 1] *= corr;
            }
            float sum = 0.f;
            #pragma unroll
            for (int nt = 0; nt < 8; nt++) {
                const float p0 = exp2f(cs[nt][2 * side]     - nm);
                const float p1 = exp2f(cs[nt][2 * side + 1] - nm);
                cs[nt][2 * side] = p0;
                cs[nt][2 * side + 1] = p1;
                sum += p0 + p1;
            }
            sum += __shfl_xor_sync(0xffffffffu, sum, 1);
            sum += __shfl_xor_sync(0xffffffffu, sum, 2);
            l[side] += sum;
        }

        /* ---- O += P Vt (Ph*Vh, Pl*Vh, Ph*Vl) ---- */
        #pragma unroll
        for (int t = 0; t < 4; t++) {
            u32 ph[4], pl[4];
            hilo2(cs[2 * t][0],     cs[2 * t][1],     ph[0], pl[0]);
            hilo2(cs[2 * t][2],     cs[2 * t][3],     ph[1], pl[1]);
            hilo2(cs[2 * t + 1][0], cs[2 * t + 1][1], ph[2], pl[2]);
            hilo2(cs[2 * t + 1][2], cs[2 * t + 1][3], ph[3], pl[3]);
            #pragma unroll
            for (int p = 0; p < 2; p++) {
                u32 vh[4], vl[4];
                ldsm4(vh, vsb[st][0] + voff + p * 2304 + t * 32);
                ldsm4(vl, vsb[st][1] + voff + p * 2304 + t * 32);
                mma4(co[2 * p],     ph, vh[0], vh[1]);
                mma4(co[2 * p],     pl, vh[0], vh[1]);
                mma4(co[2 * p],     ph, vl[0], vl[1]);
                mma4(co[2 * p + 1], ph, vh[2], vh[3]);
                mma4(co[2 * p + 1], pl, vh[2], vh[3]);
                mma4(co[2 * p + 1], ph, vl[2], vl[3]);
            }
        }
        __syncthreads();
    }

    /* ---- epilogue: out (b, n, c) ---- */
    #pragma unroll
    for (int side = 0; side < 2; side++) {
        const int row = m0 + wid * 16 + g + 8 * side;
        if (row >= NQ) continue;
        const float inv = 1.f / l[side];
        float* op = out + ((size_t)b * NQ + row) * C + h * DH;
        #pragma unroll
        for (int nt = 0; nt < 4; nt++) {
            float2 v;
            v.x = co[nt][2 * side] * inv;
            v.y = co[nt][2 * side + 1] * inv;
            *(float2*)(op + nt * 8 + 2 * tig) = v;
        }
    }
}

/* ================================================================= */
extern "C" void kernel_launch(void* const* d_in, const int* in_sizes, int n_in,
                              void* d_out, int out_size)
{
    const int base = n_in - 26;
    const float* x = (const float*)d_in[0];
    auto in = [&](int i) { return (const float*)d_in[base + i]; };

    float *tq, *tk, *tv, *qh, *kh, *oa;
    u32 *kph, *kpl, *vph, *vpl;
    cudaGetSymbolAddress((void**)&tq,  g_tq);
    cudaGetSymbolAddress((void**)&tk,  g_tk);
    cudaGetSymbolAddress((void**)&tv,  g_tv);
    cudaGetSymbolAddress((void**)&qh,  g_q);
    cudaGetSymbolAddress((void**)&kh,  g_k);
    cudaGetSymbolAddress((void**)&kph, g_kph);
    cudaGetSymbolAddress((void**)&kpl, g_kpl);
    cudaGetSymbolAddress((void**)&vph, g_vph);
    cudaGetSymbolAddress((void**)&vpl, g_vpl);
    cudaGetSymbolAddress((void**)&oa,  g_oa);

    dw_bn_s1<<<dim3(HH, BATCH), C>>>(x, in(0), in(1), in(2), in(3), in(4), in(5), tq);
    dw_bn_s2<<<dim3(HK, BATCH), C>>>(x,
                                     in(8),  in(9),  in(10), in(11), in(12), in(13),
                                     in(16), in(17), in(18), in(19), in(20), in(21),
                                     tk, tv);

    qkv_gemm<<<dim3(NTQ + 2 * NTKV, 2, BATCH), 256>>>(
        in(6),  tq, in(7),  qh,
        in(14), tk, in(15), kh,
        in(22), tv, in(23), vph, vpl);

    pack_k<<<dim3(13, HEADS, BATCH), 256>>>(kh, kph, kpl, vph, vpl);

    attn_mma<<<dim3((NQ + 127) / 128, HEADS, BATCH), 256>>>(qh, kph, kpl, vph, vpl, oa);

    proj_gemm<<<dim3(NTQ, 2, BATCH), 256>>>(in(24), oa, in(25), (float*)d_out);
}